// round 7
// baseline (speedup 1.0000x reference)
#include <cuda_runtime.h>
#include <cuda_fp16.h>
#include <math.h>
#include <stdint.h>

#define N_TOK 2048
#define D_DIM 1024
#define E_NUM 8
#define K_TOP 2
#define H_DIM 2048
#define NK (N_TOK*K_TOP)
#define Z_COEF 1e-4f

// ---------------- fp16 scratch (device globals; no allocs allowed) ----------------
__device__ __half g_x16[(size_t)N_TOK*D_DIM];
__device__ __half g_h16[(size_t)NK*H_DIM];
__device__ __half g_hsh16[(size_t)N_TOK*H_DIM];
__device__ float  g_pairout[(size_t)NK*D_DIM];

// ---------------- router scratch ----------------
__device__ int   g_topk[NK];
__device__ float g_wts[NK];
__device__ int   g_cnt[E_NUM];
__device__ int   g_off[E_NUM];
__device__ int   g_cursor[E_NUM];
__device__ int   g_rowtok[NK];
__device__ float g_roww[NK];
__device__ int   g_pos[NK];
__device__ float g_psum[E_NUM];
__device__ float g_z2;

// ============================ PTX helpers ============================
__device__ __forceinline__ uint32_t smem_u32(const void* p){
    uint32_t a;
    asm("{ .reg .u64 t; cvta.to.shared.u64 t, %1; cvt.u32.u64 %0, t; }" : "=r"(a) : "l"(p));
    return a;
}
__device__ __forceinline__ void cp16(uint32_t dst, const void* src, uint32_t sz){
    asm volatile("cp.async.cg.shared.global [%0], [%1], 16, %2;"
                 :: "r"(dst), "l"(src), "r"(sz) : "memory");
}
__device__ __forceinline__ void cp_commit(){ asm volatile("cp.async.commit_group;" ::: "memory"); }
__device__ __forceinline__ void ldsm4(uint32_t* r, uint32_t addr){
    asm volatile("ldmatrix.sync.aligned.m8n8.x4.shared.b16 {%0,%1,%2,%3}, [%4];"
                 : "=r"(r[0]), "=r"(r[1]), "=r"(r[2]), "=r"(r[3]) : "r"(addr));
}
__device__ __forceinline__ void mma16816(float* c, const uint32_t* a, const uint32_t* b){
    asm volatile("mma.sync.aligned.m16n8k16.row.col.f32.f16.f16.f32 "
                 "{%0,%1,%2,%3}, {%4,%5,%6,%7}, {%8,%9}, {%0,%1,%2,%3};"
                 : "+f"(c[0]), "+f"(c[1]), "+f"(c[2]), "+f"(c[3])
                 : "r"(a[0]), "r"(a[1]), "r"(a[2]), "r"(a[3]), "r"(b[0]), "r"(b[1]));
}
#define CP_WAIT(N) asm volatile("cp.async.wait_group %0;" :: "n"(N) : "memory")

__device__ __forceinline__ uint4 pack8(const float4 a, const float4 b){
    uint4 v;
    __half2 h0 = __floats2half2_rn(a.x, a.y);
    __half2 h1 = __floats2half2_rn(a.z, a.w);
    __half2 h2 = __floats2half2_rn(b.x, b.y);
    __half2 h3 = __floats2half2_rn(b.z, b.w);
    v.x = *(uint32_t*)&h0; v.y = *(uint32_t*)&h1;
    v.z = *(uint32_t*)&h2; v.w = *(uint32_t*)&h3;
    return v;
}

// ============================ prepass: x fp32->fp16 + per-launch init ============================
__global__ void convert_x_kernel(const float4* __restrict__ src, uint2* __restrict__ dst, int n4){
    int i = blockIdx.x*256 + threadIdx.x;
    if (blockIdx.x == 0) {
        int t = threadIdx.x;
        if (t < E_NUM) { g_cnt[t] = 0; g_cursor[t] = 0; g_psum[t] = 0.f; }
        if (t == E_NUM) g_z2 = 0.f;
    }
    if (i >= n4) return;
    float4 v = src[i];
    __half2 a = __floats2half2_rn(v.x, v.y);
    __half2 b = __floats2half2_rn(v.z, v.w);
    uint2 o;
    o.x = *(uint32_t*)&a;
    o.y = *(uint32_t*)&b;
    dst[i] = o;
}

// ============================ router (fp32, exact) ============================
__global__ void router_kernel(const float* __restrict__ x,
                              const float* __restrict__ rw,
                              const float* __restrict__ rb) {
    int n = blockIdx.x;
    int tid = threadIdx.x;
    __shared__ float xs[D_DIM];
    __shared__ float lg[E_NUM];
    const float* xrow = x + (size_t)n * D_DIM;
    for (int i = tid; i < D_DIM; i += 256) xs[i] = xrow[i];
    __syncthreads();

    int w = tid >> 5, lane = tid & 31;
    const float* wr = rw + (size_t)w * D_DIM;
    float s = 0.f;
    for (int i = lane; i < D_DIM; i += 32) s += xs[i] * wr[i];
    #pragma unroll
    for (int o = 16; o; o >>= 1) s += __shfl_xor_sync(0xffffffff, s, o);
    if (lane == 0) lg[w] = s;
    __syncthreads();

    if (tid == 0) {
        float l[E_NUM];
        #pragma unroll
        for (int e = 0; e < E_NUM; e++) l[e] = lg[e];

        int e0 = 0; float b0 = l[0] + rb[0];
        #pragma unroll
        for (int e = 1; e < E_NUM; e++) { float be = l[e] + rb[e]; if (be > b0) { b0 = be; e0 = e; } }
        int e1 = -1; float b1 = -1e30f;
        #pragma unroll
        for (int e = 0; e < E_NUM; e++) {
            if (e == e0) continue;
            float be = l[e] + rb[e];
            if (be > b1) { b1 = be; e1 = e; }
        }

        float l0 = l[e0], l1 = l[e1];
        float m2 = fmaxf(l0, l1);
        float w0 = expf(l0 - m2), w1 = expf(l1 - m2);
        float inv = 1.f / (w0 + w1);
        w0 *= inv; w1 *= inv;

        float mx = l[0];
        #pragma unroll
        for (int e = 1; e < E_NUM; e++) mx = fmaxf(mx, l[e]);
        float pe[E_NUM]; float se = 0.f;
        #pragma unroll
        for (int e = 0; e < E_NUM; e++) { pe[e] = expf(l[e] - mx); se += pe[e]; }
        float z = mx + logf(se);
        atomicAdd(&g_z2, z * z);
        float invse = 1.f / se;
        #pragma unroll
        for (int e = 0; e < E_NUM; e++) atomicAdd(&g_psum[e], pe[e] * invse);

        atomicAdd(&g_cnt[e0], 1);
        atomicAdd(&g_cnt[e1], 1);
        g_topk[n * 2 + 0] = e0; g_topk[n * 2 + 1] = e1;
        g_wts[n * 2 + 0]  = w0; g_wts[n * 2 + 1]  = w1;
    }
}

// ============================ finalize + scatter (single block) ============================
__global__ void finalize_scatter_kernel(float* __restrict__ out_scalars, int have_scalars) {
    if (threadIdx.x == 0) {
        int acc = 0;
        for (int e = 0; e < E_NUM; e++) { g_off[e] = acc; acc += g_cnt[e]; }
        if (have_scalars) {
            float lb = 0.f;
            for (int e = 0; e < E_NUM; e++)
                lb += (g_psum[e] / (float)N_TOK) * ((float)g_cnt[e] / (float)N_TOK);
            lb *= (float)E_NUM;
            out_scalars[0] = 0.f;
            out_scalars[1] = g_z2 / (float)N_TOK * Z_COEF;
            out_scalars[2] = lb;
        }
    }
    __syncthreads();
    for (int i = threadIdx.x; i < NK; i += 256) {
        int e = g_topk[i];
        int p = g_off[e] + atomicAdd(&g_cursor[e], 1);
        g_rowtok[p] = i >> 1;
        g_roww[p]   = g_wts[i];
        g_pos[i]    = p;
    }
}

// ============================ tensor-core GEMMs (mma.sync HMMA) ============================
// Tile: BM=128, BN=64, BK=32. 8 warps as 4(M) x 2(N); warp tile 32x32.
// 3-stage ring, ONE __syncthreads per stage. A (fp16) via cp.async 2 ahead;
// W (fp32) via LDG->cvt->STS fp16, LDG issued before MMA (full stage of cover).
#define LDR 80
#define GU_BG 10240
#define GU_BU 15360
#define GU_STG 20480
#define GU_SMEM (3*GU_STG)
#define DN_B  10240
#define DN_STG 15360
#define DN_SMEM (3*DN_STG)

__global__ __launch_bounds__(256) void gateup_mma(
    const float* __restrict__ GateW, const float* __restrict__ UpW,
    const float* __restrict__ ShG,   const float* __restrict__ ShU)
{
    int grp = blockIdx.z;
    bool routed = grp < E_NUM;
    int rbase = routed ? g_off[grp] : 0;
    int rcnt  = routed ? g_cnt[grp] : N_TOK;
    int m0 = blockIdx.y * 128;
    if (m0 >= rcnt) return;
    int n0 = blockIdx.x * 64;

    const float* Wg = routed ? GateW + (size_t)grp * H_DIM * D_DIM : ShG;
    const float* Wu = routed ? UpW   + (size_t)grp * H_DIM * D_DIM : ShU;
    __half* Hout = routed ? g_h16 : g_hsh16;

    extern __shared__ __align__(16) char smem[];
    uint32_t sb = smem_u32(smem);
    int tid = threadIdx.x;

    int rA0 = tid >> 2, rA1 = rA0 + 64, seg = tid & 3;
    const __half *asrc0 = g_x16, *asrc1 = g_x16;
    uint32_t av0 = 0, av1 = 0;
    if (m0 + rA0 < rcnt) {
        int tk = routed ? g_rowtok[rbase + m0 + rA0] : m0 + rA0;
        asrc0 = g_x16 + (size_t)tk * D_DIM + seg * 8; av0 = 16;
    }
    if (m0 + rA1 < rcnt) {
        int tk = routed ? g_rowtok[rbase + m0 + rA1] : m0 + rA1;
        asrc1 = g_x16 + (size_t)tk * D_DIM + seg * 8; av1 = 16;
    }
    const float* gw = Wg + (size_t)(n0 + rA0) * D_DIM + seg * 8;
    const float* uw = Wu + (size_t)(n0 + rA0) * D_DIM + seg * 8;

    uint32_t dA0 = sb + rA0 * LDR + seg * 16;
    uint32_t dA1 = sb + rA1 * LDR + seg * 16;
    uint32_t dG  = GU_BG + rA0 * LDR + seg * 16;   // byte offsets in smem[]
    uint32_t dU  = GU_BU + rA0 * LDR + seg * 16;

    float4 wg0, wg1, wu0, wu1;
    auto ldg_w = [&](int s) {
        const float4* gp = (const float4*)(gw + s * 32);
        const float4* up = (const float4*)(uw + s * 32);
        wg0 = gp[0]; wg1 = gp[1];
        wu0 = up[0]; wu1 = up[1];
    };
    auto sts_w = [&](int buf) {
        uint32_t o = (uint32_t)buf * GU_STG;
        *(uint4*)(smem + dG + o) = pack8(wg0, wg1);
        *(uint4*)(smem + dU + o) = pack8(wu0, wu1);
    };
    auto cp_a = [&](int s) {
        uint32_t o = (uint32_t)(s % 3) * GU_STG;
        cp16(dA0 + o, asrc0 + s * 32, av0);
        cp16(dA1 + o, asrc1 + s * 32, av1);
        cp_commit();
    };

    const int S = D_DIM / 32;   // 32
    ldg_w(0); sts_w(0); cp_a(0);
    ldg_w(1); cp_a(1);

    int warp = tid >> 5, lane = tid & 31;
    int wm = warp & 3, wn = warp >> 2;
    int g = lane >> 3;
    int brow = ((g >> 1) << 3) + (lane & 7);
    int bks = (g & 1) << 4;

    float cg[2][4][4] = {}, cu[2][4][4] = {};

    #pragma unroll 1
    for (int s = 0; s < S; s++) {
        if (s + 1 < S) CP_WAIT(1);
        else           CP_WAIT(0);
        __syncthreads();   // single barrier per stage (3-buffer ring makes tail sync unnecessary)
        uint32_t o = sb + (uint32_t)(s % 3) * GU_STG;

        uint32_t a[2][2][4];
        #pragma unroll
        for (int mt = 0; mt < 2; mt++)
            #pragma unroll
            for (int kt = 0; kt < 2; kt++)
                ldsm4(a[mt][kt], o + (wm * 32 + mt * 16 + (lane & 15)) * LDR + kt * 32 + (lane >> 4) * 16);

        uint32_t bg[2][2][4], bu[2][2][4];
        #pragma unroll
        for (int nt = 0; nt < 2; nt++)
            #pragma unroll
            for (int kt = 0; kt < 2; kt++) {
                uint32_t ro = (wn * 32 + nt * 16 + brow) * LDR + kt * 32 + bks;
                ldsm4(bg[nt][kt], o + GU_BG + ro);
                ldsm4(bu[nt][kt], o + GU_BU + ro);
            }

        // stage s+1 weights: regs were LDG'd a full stage ago; STS drains under the MMAs
        if (s + 1 < S) sts_w((s + 1) % 3);
        // prefetch stage s+2 weights: the MMA section below covers the DRAM latency
        if (s + 2 < S) ldg_w(s + 2);

        #pragma unroll
        for (int mt = 0; mt < 2; mt++)
            #pragma unroll
            for (int nt = 0; nt < 2; nt++)
                #pragma unroll
                for (int kt = 0; kt < 2; kt++) {
                    mma16816(cg[mt][nt * 2 + 0], a[mt][kt], &bg[nt][kt][0]);
                    mma16816(cg[mt][nt * 2 + 1], a[mt][kt], &bg[nt][kt][2]);
                    mma16816(cu[mt][nt * 2 + 0], a[mt][kt], &bu[nt][kt][0]);
                    mma16816(cu[mt][nt * 2 + 1], a[mt][kt], &bu[nt][kt][2]);
                }

        if (s + 2 < S) cp_a(s + 2);
    }

    #pragma unroll
    for (int mt = 0; mt < 2; mt++) {
        int rbaserow = m0 + wm * 32 + mt * 16 + (lane >> 2);
        #pragma unroll
        for (int h = 0; h < 2; h++) {
            int r = rbaserow + h * 8;
            if (r >= rcnt) continue;
            __half* hp = Hout + (size_t)(rbase + r) * H_DIM + n0 + wn * 32 + (lane & 3) * 2;
            #pragma unroll
            for (int j = 0; j < 4; j++) {
                float g0 = cg[mt][j][h * 2 + 0], g1 = cg[mt][j][h * 2 + 1];
                float u0 = cu[mt][j][h * 2 + 0], u1 = cu[mt][j][h * 2 + 1];
                float h0 = g0 * u0 / (1.f + __expf(-g0));
                float h1 = g1 * u1 / (1.f + __expf(-g1));
                *(__half2*)(hp + j * 8) = __floats2half2_rn(h0, h1);
            }
        }
    }
}

__global__ __launch_bounds__(256) void down_mma(
    const float* __restrict__ DownW, const float* __restrict__ ShD,
    float* __restrict__ Out)
{
    int grp = blockIdx.z;
    bool routed = grp < E_NUM;
    int rbase = routed ? g_off[grp] : 0;
    int rcnt  = routed ? g_cnt[grp] : N_TOK;
    int m0 = blockIdx.y * 128;
    if (m0 >= rcnt) return;
    int n0 = blockIdx.x * 64;

    const float* Wd  = routed ? DownW + (size_t)grp * D_DIM * H_DIM : ShD;
    const __half* Hin = routed ? g_h16 : g_hsh16;

    extern __shared__ __align__(16) char smem[];
    uint32_t sb = smem_u32(smem);
    int tid = threadIdx.x;

    int rA0 = tid >> 2, rA1 = rA0 + 64, seg = tid & 3;
    const __half *asrc0 = Hin, *asrc1 = Hin;
    uint32_t av0 = 0, av1 = 0;
    if (m0 + rA0 < rcnt) { asrc0 = Hin + (size_t)(rbase + m0 + rA0) * H_DIM + seg * 8; av0 = 16; }
    if (m0 + rA1 < rcnt) { asrc1 = Hin + (size_t)(rbase + m0 + rA1) * H_DIM + seg * 8; av1 = 16; }
    const float* dw = Wd + (size_t)(n0 + rA0) * H_DIM + seg * 8;

    uint32_t dA0 = sb + rA0 * LDR + seg * 16;
    uint32_t dA1 = sb + rA1 * LDR + seg * 16;
    uint32_t dB  = DN_B + rA0 * LDR + seg * 16;

    float4 wd0, wd1;
    auto ldg_w = [&](int s) {
        const float4* p = (const float4*)(dw + s * 32);
        wd0 = p[0]; wd1 = p[1];
    };
    auto sts_w = [&](int buf) {
        *(uint4*)(smem + dB + (uint32_t)buf * DN_STG) = pack8(wd0, wd1);
    };
    auto cp_a = [&](int s) {
        uint32_t o = (uint32_t)(s % 3) * DN_STG;
        cp16(dA0 + o, asrc0 + s * 32, av0);
        cp16(dA1 + o, asrc1 + s * 32, av1);
        cp_commit();
    };

    const int S = H_DIM / 32;   // 64
    ldg_w(0); sts_w(0); cp_a(0);
    ldg_w(1); cp_a(1);

    int warp = tid >> 5, lane = tid & 31;
    int wm = warp & 3, wn = warp >> 2;
    int g = lane >> 3;
    int brow = ((g >> 1) << 3) + (lane & 7);
    int bks = (g & 1) << 4;

    float c[2][4][4] = {};

    #pragma unroll 1
    for (int s = 0; s < S; s++) {
        if (s + 1 < S) CP_WAIT(1);
        else           CP_WAIT(0);
        __syncthreads();
        uint32_t o = sb + (uint32_t)(s % 3) * DN_STG;

        uint32_t a[2][2][4];
        #pragma unroll
        for (int mt = 0; mt < 2; mt++)
            #pragma unroll
            for (int kt = 0; kt < 2; kt++)
                ldsm4(a[mt][kt], o + (wm * 32 + mt * 16 + (lane & 15)) * LDR + kt * 32 + (lane >> 4) * 16);

        uint32_t b[2][2][4];
        #pragma unroll
        for (int nt = 0; nt < 2; nt++)
            #pragma unroll
            for (int kt = 0; kt < 2; kt++)
                ldsm4(b[nt][kt], o + DN_B + (wn * 32 + nt * 16 + brow) * LDR + kt * 32 + bks);

        if (s + 1 < S) sts_w((s + 1) % 3);
        if (s + 2 < S) ldg_w(s + 2);

        #pragma unroll
        for (int mt = 0; mt < 2; mt++)
            #pragma unroll
            for (int nt = 0; nt < 2; nt++)
                #pragma unroll
                for (int kt = 0; kt < 2; kt++) {
                    mma16816(c[mt][nt * 2 + 0], a[mt][kt], &b[nt][kt][0]);
                    mma16816(c[mt][nt * 2 + 1], a[mt][kt], &b[nt][kt][2]);
                }

        if (s + 2 < S) cp_a(s + 2);
    }

    #pragma unroll
    for (int mt = 0; mt < 2; mt++) {
        int rbaserow = m0 + wm * 32 + mt * 16 + (lane >> 2);
        #pragma unroll
        for (int h = 0; h < 2; h++) {
            int r = rbaserow + h * 8;
            if (r >= rcnt) continue;
            float w = routed ? g_roww[rbase + r] : 1.f;
            float* op = (routed ? g_pairout + (size_t)(rbase + r) * D_DIM
                                : Out + (size_t)r * D_DIM)
                        + n0 + wn * 32 + (lane & 3) * 2;
            #pragma unroll
            for (int j = 0; j < 4; j++) {
                float2 v = make_float2(c[mt][j][h * 2 + 0] * w, c[mt][j][h * 2 + 1] * w);
                *(float2*)(op + j * 8) = v;
            }
        }
    }
}

// ============================ combine ============================
__global__ void combine_kernel(float* __restrict__ out) {
    int i4 = blockIdx.x * 256 + threadIdx.x;
    const int total4 = N_TOK * D_DIM / 4;
    if (i4 >= total4) return;
    int n  = i4 / (D_DIM / 4);
    int d4 = i4 % (D_DIM / 4);
    int p0 = g_pos[n * 2 + 0];
    int p1 = g_pos[n * 2 + 1];
    const float4* pr = (const float4*)g_pairout;
    float4 o = ((float4*)out)[i4];
    float4 a = pr[(size_t)p0 * (D_DIM / 4) + d4];
    float4 b = pr[(size_t)p1 * (D_DIM / 4) + d4];
    o.x += a.x + b.x; o.y += a.y + b.y; o.z += a.z + b.z; o.w += a.w + b.w;
    ((float4*)out)[i4] = o;
}

// ============================ launch ============================
extern "C" void kernel_launch(void* const* d_in, const int* in_sizes, int n_in,
                              void* d_out, int out_size) {
    const float* x      = (const float*)d_in[0];
    const float* rw     = (const float*)d_in[1];
    const float* rb     = (const float*)d_in[2];
    const float* gate_w = (const float*)d_in[3];
    const float* up_w   = (const float*)d_in[4];
    const float* down_w = (const float*)d_in[5];
    const float* shg    = (const float*)d_in[6];
    const float* shu    = (const float*)d_in[7];
    const float* shd    = (const float*)d_in[8];
    float* out = (float*)d_out;

    const int hid_elems = N_TOK * D_DIM;
    int have_scalars = (out_size >= hid_elems + 3) ? 1 : 0;

    void* p_x16;
    cudaGetSymbolAddress(&p_x16, g_x16);

    cudaFuncSetAttribute(gateup_mma, cudaFuncAttributeMaxDynamicSharedMemorySize, GU_SMEM);
    cudaFuncSetAttribute(down_mma,   cudaFuncAttributeMaxDynamicSharedMemorySize, DN_SMEM);

    const int n4_x = N_TOK * D_DIM / 4;
    convert_x_kernel<<<n4_x / 256, 256>>>((const float4*)x, (uint2*)p_x16, n4_x);

    router_kernel<<<N_TOK, 256>>>(x, rw, rb);
    finalize_scatter_kernel<<<1, 256>>>(out + hid_elems, have_scalars);

    gateup_mma<<<dim3(H_DIM / 64, 16, 9), 256, GU_SMEM>>>(gate_w, up_w, shg, shu);
    down_mma<<<dim3(D_DIM / 64, 16, 9), 256, DN_SMEM>>>(down_w, shd, out);

    combine_kernel<<<(N_TOK * D_DIM / 4 + 255) / 256, 256>>>(out);
}

// round 8
// speedup vs baseline: 1.1724x; 1.1724x over previous
#include <cuda_runtime.h>
#include <cuda_fp16.h>
#include <math.h>
#include <stdint.h>

#define N_TOK 2048
#define D_DIM 1024
#define E_NUM 8
#define K_TOP 2
#define H_DIM 2048
#define NK (N_TOK*K_TOP)
#define Z_COEF 1e-4f

// ---------------- fp16 scratch (device globals; no allocs allowed) ----------------
__device__ __half g_x16[(size_t)N_TOK*D_DIM];
__device__ __half g_h16[(size_t)NK*H_DIM];
__device__ __half g_hsh16[(size_t)N_TOK*H_DIM];
__device__ float  g_pairout[(size_t)NK*D_DIM];

// ---------------- router scratch ----------------
__device__ int   g_topk[NK];
__device__ float g_wts[NK];
__device__ int   g_cnt[E_NUM];
__device__ int   g_off[E_NUM];
__device__ int   g_cursor[E_NUM];
__device__ int   g_rowtok[NK];
__device__ float g_roww[NK];
__device__ int   g_pos[NK];
__device__ float g_psum[E_NUM];
__device__ float g_z2;

// ============================ PTX helpers ============================
__device__ __forceinline__ uint32_t smem_u32(const void* p){
    uint32_t a;
    asm("{ .reg .u64 t; cvta.to.shared.u64 t, %1; cvt.u32.u64 %0, t; }" : "=r"(a) : "l"(p));
    return a;
}
__device__ __forceinline__ void cp16(uint32_t dst, const void* src, uint32_t sz){
    asm volatile("cp.async.cg.shared.global [%0], [%1], 16, %2;"
                 :: "r"(dst), "l"(src), "r"(sz) : "memory");
}
__device__ __forceinline__ void cp_commit(){ asm volatile("cp.async.commit_group;" ::: "memory"); }
__device__ __forceinline__ void ldsm4(uint32_t* r, uint32_t addr){
    asm volatile("ldmatrix.sync.aligned.m8n8.x4.shared.b16 {%0,%1,%2,%3}, [%4];"
                 : "=r"(r[0]), "=r"(r[1]), "=r"(r[2]), "=r"(r[3]) : "r"(addr));
}
__device__ __forceinline__ void mma16816(float* c, const uint32_t* a, const uint32_t* b){
    asm volatile("mma.sync.aligned.m16n8k16.row.col.f32.f16.f16.f32 "
                 "{%0,%1,%2,%3}, {%4,%5,%6,%7}, {%8,%9}, {%0,%1,%2,%3};"
                 : "+f"(c[0]), "+f"(c[1]), "+f"(c[2]), "+f"(c[3])
                 : "r"(a[0]), "r"(a[1]), "r"(a[2]), "r"(a[3]), "r"(b[0]), "r"(b[1]));
}
#define CP_WAIT(N) asm volatile("cp.async.wait_group %0;" :: "n"(N) : "memory")

__device__ __forceinline__ uint4 pack8(const float4 a, const float4 b){
    uint4 v;
    __half2 h0 = __floats2half2_rn(a.x, a.y);
    __half2 h1 = __floats2half2_rn(a.z, a.w);
    __half2 h2 = __floats2half2_rn(b.x, b.y);
    __half2 h3 = __floats2half2_rn(b.z, b.w);
    v.x = *(uint32_t*)&h0; v.y = *(uint32_t*)&h1;
    v.z = *(uint32_t*)&h2; v.w = *(uint32_t*)&h3;
    return v;
}

// ============================ prepass: x fp32->fp16 + per-launch init ============================
__global__ void convert_x_kernel(const float4* __restrict__ src, uint2* __restrict__ dst, int n4){
    int i = blockIdx.x*256 + threadIdx.x;
    if (blockIdx.x == 0) {
        int t = threadIdx.x;
        if (t < E_NUM) { g_cnt[t] = 0; g_cursor[t] = 0; g_psum[t] = 0.f; }
        if (t == E_NUM) g_z2 = 0.f;
    }
    if (i >= n4) return;
    float4 v = src[i];
    __half2 a = __floats2half2_rn(v.x, v.y);
    __half2 b = __floats2half2_rn(v.z, v.w);
    uint2 o;
    o.x = *(uint32_t*)&a;
    o.y = *(uint32_t*)&b;
    dst[i] = o;
}

// ============================ router (fp32, exact) ============================
__global__ void router_kernel(const float* __restrict__ x,
                              const float* __restrict__ rw,
                              const float* __restrict__ rb) {
    int n = blockIdx.x;
    int tid = threadIdx.x;
    __shared__ float xs[D_DIM];
    __shared__ float lg[E_NUM];
    const float* xrow = x + (size_t)n * D_DIM;
    for (int i = tid; i < D_DIM; i += 256) xs[i] = xrow[i];
    __syncthreads();

    int w = tid >> 5, lane = tid & 31;
    const float* wr = rw + (size_t)w * D_DIM;
    float s = 0.f;
    for (int i = lane; i < D_DIM; i += 32) s += xs[i] * wr[i];
    #pragma unroll
    for (int o = 16; o; o >>= 1) s += __shfl_xor_sync(0xffffffff, s, o);
    if (lane == 0) lg[w] = s;
    __syncthreads();

    if (tid == 0) {
        float l[E_NUM];
        #pragma unroll
        for (int e = 0; e < E_NUM; e++) l[e] = lg[e];

        int e0 = 0; float b0 = l[0] + rb[0];
        #pragma unroll
        for (int e = 1; e < E_NUM; e++) { float be = l[e] + rb[e]; if (be > b0) { b0 = be; e0 = e; } }
        int e1 = -1; float b1 = -1e30f;
        #pragma unroll
        for (int e = 0; e < E_NUM; e++) {
            if (e == e0) continue;
            float be = l[e] + rb[e];
            if (be > b1) { b1 = be; e1 = e; }
        }

        float l0 = l[e0], l1 = l[e1];
        float m2 = fmaxf(l0, l1);
        float w0 = expf(l0 - m2), w1 = expf(l1 - m2);
        float inv = 1.f / (w0 + w1);
        w0 *= inv; w1 *= inv;

        float mx = l[0];
        #pragma unroll
        for (int e = 1; e < E_NUM; e++) mx = fmaxf(mx, l[e]);
        float pe[E_NUM]; float se = 0.f;
        #pragma unroll
        for (int e = 0; e < E_NUM; e++) { pe[e] = expf(l[e] - mx); se += pe[e]; }
        float z = mx + logf(se);
        atomicAdd(&g_z2, z * z);
        float invse = 1.f / se;
        #pragma unroll
        for (int e = 0; e < E_NUM; e++) atomicAdd(&g_psum[e], pe[e] * invse);

        atomicAdd(&g_cnt[e0], 1);
        atomicAdd(&g_cnt[e1], 1);
        g_topk[n * 2 + 0] = e0; g_topk[n * 2 + 1] = e1;
        g_wts[n * 2 + 0]  = w0; g_wts[n * 2 + 1]  = w1;
    }
}

// ============================ finalize + scatter (single block) ============================
__global__ void finalize_scatter_kernel(float* __restrict__ out_scalars, int have_scalars) {
    if (threadIdx.x == 0) {
        int acc = 0;
        for (int e = 0; e < E_NUM; e++) { g_off[e] = acc; acc += g_cnt[e]; }
        if (have_scalars) {
            float lb = 0.f;
            for (int e = 0; e < E_NUM; e++)
                lb += (g_psum[e] / (float)N_TOK) * ((float)g_cnt[e] / (float)N_TOK);
            lb *= (float)E_NUM;
            out_scalars[0] = 0.f;
            out_scalars[1] = g_z2 / (float)N_TOK * Z_COEF;
            out_scalars[2] = lb;
        }
    }
    __syncthreads();
    for (int i = threadIdx.x; i < NK; i += 256) {
        int e = g_topk[i];
        int p = g_off[e] + atomicAdd(&g_cursor[e], 1);
        g_rowtok[p] = i >> 1;
        g_roww[p]   = g_wts[i];
        g_pos[i]    = p;
    }
}

// ============================ tensor-core GEMMs (mma.sync HMMA) ============================
// Tile: BM=128, BN=64, BK=32. 8 warps as 4(M) x 2(N); warp tile 32x32 per output.
// A (fp16 activations) via cp.async double-buffer; W (fp32 weights) via
// LDG->cvt->STS fp16, software-pipelined. smem rows padded to 40 halves (80B).
// (R5 mainloop structure, verbatim — fastest measured configuration.)
#define LDR 80
#define GU_BG 10240
#define GU_BU 15360
#define GU_STG 20480
#define DN_B  10240
#define DN_STG 15360

__global__ __launch_bounds__(256) void gateup_mma(
    const float* __restrict__ GateW, const float* __restrict__ UpW,
    const float* __restrict__ ShG,   const float* __restrict__ ShU)
{
    int grp = blockIdx.z;
    bool routed = grp < E_NUM;
    int rbase = routed ? g_off[grp] : 0;
    int rcnt  = routed ? g_cnt[grp] : N_TOK;
    int m0 = blockIdx.y * 128;
    if (m0 >= rcnt) return;
    int n0 = blockIdx.x * 64;

    const float* Wg = routed ? GateW + (size_t)grp * H_DIM * D_DIM : ShG;
    const float* Wu = routed ? UpW   + (size_t)grp * H_DIM * D_DIM : ShU;
    __half* Hout = routed ? g_h16 : g_hsh16;

    __shared__ __align__(16) char smem[2 * GU_STG];
    uint32_t sb = smem_u32(smem);
    int tid = threadIdx.x;

    int rA0 = tid >> 2, rA1 = rA0 + 64, seg = tid & 3;
    const __half *asrc0 = g_x16, *asrc1 = g_x16;
    uint32_t av0 = 0, av1 = 0;
    if (m0 + rA0 < rcnt) {
        int tk = routed ? g_rowtok[rbase + m0 + rA0] : m0 + rA0;
        asrc0 = g_x16 + (size_t)tk * D_DIM + seg * 8; av0 = 16;
    }
    if (m0 + rA1 < rcnt) {
        int tk = routed ? g_rowtok[rbase + m0 + rA1] : m0 + rA1;
        asrc1 = g_x16 + (size_t)tk * D_DIM + seg * 8; av1 = 16;
    }
    const float* gw = Wg + (size_t)(n0 + rA0) * D_DIM + seg * 8;
    const float* uw = Wu + (size_t)(n0 + rA0) * D_DIM + seg * 8;

    uint32_t dA0 = sb + rA0 * LDR + seg * 16;
    uint32_t dA1 = sb + rA1 * LDR + seg * 16;
    uint32_t dG  = sb + GU_BG + rA0 * LDR + seg * 16;
    uint32_t dU  = sb + GU_BU + rA0 * LDR + seg * 16;

    float4 wg0, wg1, wu0, wu1;
    auto ldg_w = [&](int s) {
        const float4* gp = (const float4*)(gw + s * 32);
        const float4* up = (const float4*)(uw + s * 32);
        wg0 = gp[0]; wg1 = gp[1];
        wu0 = up[0]; wu1 = up[1];
    };
    auto sts_w = [&](int buf) {
        uint32_t o = (uint32_t)buf * GU_STG;
        *(uint4*)(smem + (dG + o - sb)) = pack8(wg0, wg1);
        *(uint4*)(smem + (dU + o - sb)) = pack8(wu0, wu1);
    };
    auto cp_a = [&](int s) {
        uint32_t o = (uint32_t)(s & 1) * GU_STG;
        cp16(dA0 + o, asrc0 + s * 32, av0);
        cp16(dA1 + o, asrc1 + s * 32, av1);
        cp_commit();
    };

    const int S = D_DIM / 32;
    ldg_w(0); sts_w(0); cp_a(0);
    ldg_w(1); cp_a(1);

    int warp = tid >> 5, lane = tid & 31;
    int wm = warp & 3, wn = warp >> 2;
    int g = lane >> 3;
    int brow = ((g >> 1) << 3) + (lane & 7);
    int bks = (g & 1) << 4;

    float cg[2][4][4] = {}, cu[2][4][4] = {};

    #pragma unroll 1
    for (int s = 0; s < S; s++) {
        if (s + 1 < S) CP_WAIT(1);
        else           CP_WAIT(0);
        __syncthreads();
        uint32_t o = sb + (uint32_t)(s & 1) * GU_STG;

        uint32_t a[2][2][4];
        #pragma unroll
        for (int mt = 0; mt < 2; mt++)
            #pragma unroll
            for (int kt = 0; kt < 2; kt++)
                ldsm4(a[mt][kt], o + (wm * 32 + mt * 16 + (lane & 15)) * LDR + kt * 32 + (lane >> 4) * 16);

        uint32_t bg[2][2][4], bu[2][2][4];
        #pragma unroll
        for (int nt = 0; nt < 2; nt++)
            #pragma unroll
            for (int kt = 0; kt < 2; kt++) {
                uint32_t ro = (wn * 32 + nt * 16 + brow) * LDR + kt * 32 + bks;
                ldsm4(bg[nt][kt], o + GU_BG + ro);
                ldsm4(bu[nt][kt], o + GU_BU + ro);
            }

        #pragma unroll
        for (int mt = 0; mt < 2; mt++)
            #pragma unroll
            for (int nt = 0; nt < 2; nt++)
                #pragma unroll
                for (int kt = 0; kt < 2; kt++) {
                    mma16816(cg[mt][nt * 2 + 0], a[mt][kt], &bg[nt][kt][0]);
                    mma16816(cg[mt][nt * 2 + 1], a[mt][kt], &bg[nt][kt][2]);
                    mma16816(cu[mt][nt * 2 + 0], a[mt][kt], &bu[nt][kt][0]);
                    mma16816(cu[mt][nt * 2 + 1], a[mt][kt], &bu[nt][kt][2]);
                }

        if (s + 1 < S) sts_w((s + 1) & 1);
        __syncthreads();
        if (s + 2 < S) { cp_a(s + 2); ldg_w(s + 2); }
    }

    #pragma unroll
    for (int mt = 0; mt < 2; mt++) {
        int rbaserow = m0 + wm * 32 + mt * 16 + (lane >> 2);
        #pragma unroll
        for (int h = 0; h < 2; h++) {
            int r = rbaserow + h * 8;
            if (r >= rcnt) continue;
            __half* hp = Hout + (size_t)(rbase + r) * H_DIM + n0 + wn * 32 + (lane & 3) * 2;
            #pragma unroll
            for (int j = 0; j < 4; j++) {
                float g0 = cg[mt][j][h * 2 + 0], g1 = cg[mt][j][h * 2 + 1];
                float u0 = cu[mt][j][h * 2 + 0], u1 = cu[mt][j][h * 2 + 1];
                float h0 = g0 * u0 / (1.f + __expf(-g0));
                float h1 = g1 * u1 / (1.f + __expf(-g1));
                *(__half2*)(hp + j * 8) = __floats2half2_rn(h0, h1);
            }
        }
    }
}

__global__ __launch_bounds__(256, 2) void down_mma(
    const float* __restrict__ DownW, const float* __restrict__ ShD,
    float* __restrict__ Out)
{
    int grp = blockIdx.z;
    bool routed = grp < E_NUM;
    int rbase = routed ? g_off[grp] : 0;
    int rcnt  = routed ? g_cnt[grp] : N_TOK;
    int m0 = blockIdx.y * 128;
    if (m0 >= rcnt) return;
    int n0 = blockIdx.x * 64;

    const float* Wd  = routed ? DownW + (size_t)grp * D_DIM * H_DIM : ShD;
    const __half* Hin = routed ? g_h16 : g_hsh16;

    __shared__ __align__(16) char smem[2 * DN_STG];
    uint32_t sb = smem_u32(smem);
    int tid = threadIdx.x;

    int rA0 = tid >> 2, rA1 = rA0 + 64, seg = tid & 3;
    const __half *asrc0 = Hin, *asrc1 = Hin;
    uint32_t av0 = 0, av1 = 0;
    if (m0 + rA0 < rcnt) { asrc0 = Hin + (size_t)(rbase + m0 + rA0) * H_DIM + seg * 8; av0 = 16; }
    if (m0 + rA1 < rcnt) { asrc1 = Hin + (size_t)(rbase + m0 + rA1) * H_DIM + seg * 8; av1 = 16; }
    const float* dw = Wd + (size_t)(n0 + rA0) * H_DIM + seg * 8;

    uint32_t dA0 = sb + rA0 * LDR + seg * 16;
    uint32_t dA1 = sb + rA1 * LDR + seg * 16;
    uint32_t dB  = sb + DN_B + rA0 * LDR + seg * 16;

    float4 wd0, wd1;
    auto ldg_w = [&](int s) {
        const float4* p = (const float4*)(dw + s * 32);
        wd0 = p[0]; wd1 = p[1];
    };
    auto sts_w = [&](int buf) {
        *(uint4*)(smem + (dB + (uint32_t)buf * DN_STG - sb)) = pack8(wd0, wd1);
    };
    auto cp_a = [&](int s) {
        uint32_t o = (uint32_t)(s & 1) * DN_STG;
        cp16(dA0 + o, asrc0 + s * 32, av0);
        cp16(dA1 + o, asrc1 + s * 32, av1);
        cp_commit();
    };

    const int S = H_DIM / 32;
    ldg_w(0); sts_w(0); cp_a(0);
    ldg_w(1); cp_a(1);

    int warp = tid >> 5, lane = tid & 31;
    int wm = warp & 3, wn = warp >> 2;
    int g = lane >> 3;
    int brow = ((g >> 1) << 3) + (lane & 7);
    int bks = (g & 1) << 4;

    float c[2][4][4] = {};

    #pragma unroll 1
    for (int s = 0; s < S; s++) {
        if (s + 1 < S) CP_WAIT(1);
        else           CP_WAIT(0);
        __syncthreads();
        uint32_t o = sb + (uint32_t)(s & 1) * DN_STG;

        uint32_t a[2][2][4];
        #pragma unroll
        for (int mt = 0; mt < 2; mt++)
            #pragma unroll
            for (int kt = 0; kt < 2; kt++)
                ldsm4(a[mt][kt], o + (wm * 32 + mt * 16 + (lane & 15)) * LDR + kt * 32 + (lane >> 4) * 16);

        uint32_t b[2][2][4];
        #pragma unroll
        for (int nt = 0; nt < 2; nt++)
            #pragma unroll
            for (int kt = 0; kt < 2; kt++)
                ldsm4(b[nt][kt], o + DN_B + (wn * 32 + nt * 16 + brow) * LDR + kt * 32 + bks);

        #pragma unroll
        for (int mt = 0; mt < 2; mt++)
            #pragma unroll
            for (int nt = 0; nt < 2; nt++)
                #pragma unroll
                for (int kt = 0; kt < 2; kt++) {
                    mma16816(c[mt][nt * 2 + 0], a[mt][kt], &b[nt][kt][0]);
                    mma16816(c[mt][nt * 2 + 1], a[mt][kt], &b[nt][kt][2]);
                }

        if (s + 1 < S) sts_w((s + 1) & 1);
        __syncthreads();
        if (s + 2 < S) { cp_a(s + 2); ldg_w(s + 2); }
    }

    #pragma unroll
    for (int mt = 0; mt < 2; mt++) {
        int rbaserow = m0 + wm * 32 + mt * 16 + (lane >> 2);
        #pragma unroll
        for (int h = 0; h < 2; h++) {
            int r = rbaserow + h * 8;
            if (r >= rcnt) continue;
            float w = routed ? g_roww[rbase + r] : 1.f;
            float* op = (routed ? g_pairout + (size_t)(rbase + r) * D_DIM
                                : Out + (size_t)r * D_DIM)
                        + n0 + wn * 32 + (lane & 3) * 2;
            #pragma unroll
            for (int j = 0; j < 4; j++) {
                float2 v = make_float2(c[mt][j][h * 2 + 0] * w, c[mt][j][h * 2 + 1] * w);
                *(float2*)(op + j * 8) = v;
            }
        }
    }
}

// ============================ combine ============================
__global__ void combine_kernel(float* __restrict__ out) {
    int i4 = blockIdx.x * 256 + threadIdx.x;
    const int total4 = N_TOK * D_DIM / 4;
    if (i4 >= total4) return;
    int n  = i4 / (D_DIM / 4);
    int d4 = i4 % (D_DIM / 4);
    int p0 = g_pos[n * 2 + 0];
    int p1 = g_pos[n * 2 + 1];
    const float4* pr = (const float4*)g_pairout;
    float4 o = ((float4*)out)[i4];
    float4 a = pr[(size_t)p0 * (D_DIM / 4) + d4];
    float4 b = pr[(size_t)p1 * (D_DIM / 4) + d4];
    o.x += a.x + b.x; o.y += a.y + b.y; o.z += a.z + b.z; o.w += a.w + b.w;
    ((float4*)out)[i4] = o;
}

// ============================ launch ============================
extern "C" void kernel_launch(void* const* d_in, const int* in_sizes, int n_in,
                              void* d_out, int out_size) {
    const float* x      = (const float*)d_in[0];
    const float* rw     = (const float*)d_in[1];
    const float* rb     = (const float*)d_in[2];
    const float* gate_w = (const float*)d_in[3];
    const float* up_w   = (const float*)d_in[4];
    const float* down_w = (const float*)d_in[5];
    const float* shg    = (const float*)d_in[6];
    const float* shu    = (const float*)d_in[7];
    const float* shd    = (const float*)d_in[8];
    float* out = (float*)d_out;

    const int hid_elems = N_TOK * D_DIM;
    int have_scalars = (out_size >= hid_elems + 3) ? 1 : 0;

    void* p_x16;
    cudaGetSymbolAddress(&p_x16, g_x16);

    const int n4_x = N_TOK * D_DIM / 4;
    convert_x_kernel<<<n4_x / 256, 256>>>((const float4*)x, (uint2*)p_x16, n4_x);

    router_kernel<<<N_TOK, 256>>>(x, rw, rb);
    finalize_scatter_kernel<<<1, 256>>>(out + hid_elems, have_scalars);

    gateup_mma<<<dim3(H_DIM / 64, 16, 9), 256>>>(gate_w, up_w, shg, shu);
    down_mma<<<dim3(D_DIM / 64, 16, 9), 256>>>(down_w, shd, out);

    combine_kernel<<<(N_TOK * D_DIM / 4 + 255) / 256, 256>>>(out);
}

// round 9
// speedup vs baseline: 1.2499x; 1.0662x over previous
#include <cuda_runtime.h>
#include <cuda_fp16.h>
#include <math.h>
#include <stdint.h>

#define N_TOK 2048
#define D_DIM 1024
#define E_NUM 8
#define K_TOP 2
#define H_DIM 2048
#define NK (N_TOK*K_TOP)
#define Z_COEF 1e-4f

// ---------------- fp16 scratch (device globals; no allocs allowed) ----------------
__device__ __half g_x16[(size_t)N_TOK*D_DIM];
__device__ __half g_h16[(size_t)NK*H_DIM];
__device__ __half g_hsh16[(size_t)N_TOK*H_DIM];
__device__ float  g_pairout[(size_t)NK*D_DIM];

// ---------------- router scratch ----------------
__device__ int   g_topk[NK];
__device__ float g_wts[NK];
__device__ float g_probs[(size_t)N_TOK*E_NUM];
__device__ float g_z[N_TOK];
__device__ int   g_cnt[E_NUM];
__device__ int   g_off[E_NUM];
__device__ int   g_rowtok[NK];
__device__ float g_roww[NK];
__device__ int   g_pos[NK];

// ============================ PTX helpers ============================
__device__ __forceinline__ uint32_t smem_u32(const void* p){
    uint32_t a;
    asm("{ .reg .u64 t; cvta.to.shared.u64 t, %1; cvt.u32.u64 %0, t; }" : "=r"(a) : "l"(p));
    return a;
}
__device__ __forceinline__ void cp16(uint32_t dst, const void* src, uint32_t sz){
    asm volatile("cp.async.cg.shared.global [%0], [%1], 16, %2;"
                 :: "r"(dst), "l"(src), "r"(sz) : "memory");
}
__device__ __forceinline__ void cp_commit(){ asm volatile("cp.async.commit_group;" ::: "memory"); }
__device__ __forceinline__ void ldsm4(uint32_t* r, uint32_t addr){
    asm volatile("ldmatrix.sync.aligned.m8n8.x4.shared.b16 {%0,%1,%2,%3}, [%4];"
                 : "=r"(r[0]), "=r"(r[1]), "=r"(r[2]), "=r"(r[3]) : "r"(addr));
}
__device__ __forceinline__ void mma16816(float* c, const uint32_t* a, const uint32_t* b){
    asm volatile("mma.sync.aligned.m16n8k16.row.col.f32.f16.f16.f32 "
                 "{%0,%1,%2,%3}, {%4,%5,%6,%7}, {%8,%9}, {%0,%1,%2,%3};"
                 : "+f"(c[0]), "+f"(c[1]), "+f"(c[2]), "+f"(c[3])
                 : "r"(a[0]), "r"(a[1]), "r"(a[2]), "r"(a[3]), "r"(b[0]), "r"(b[1]));
}
#define CP_WAIT(N) asm volatile("cp.async.wait_group %0;" :: "n"(N) : "memory")

__device__ __forceinline__ uint4 pack8(const float4 a, const float4 b){
    uint4 v;
    __half2 h0 = __floats2half2_rn(a.x, a.y);
    __half2 h1 = __floats2half2_rn(a.z, a.w);
    __half2 h2 = __floats2half2_rn(b.x, b.y);
    __half2 h3 = __floats2half2_rn(b.z, b.w);
    v.x = *(uint32_t*)&h0; v.y = *(uint32_t*)&h1;
    v.z = *(uint32_t*)&h2; v.w = *(uint32_t*)&h3;
    return v;
}

// ============================ router + x convert (fused, atomic-free) ============================
__global__ __launch_bounds__(256) void router_convert_kernel(
    const float4* __restrict__ x4, const float* __restrict__ rw,
    const float* __restrict__ rb,  uint2* __restrict__ x16)
{
    int n = blockIdx.x;
    int tid = threadIdx.x;
    __shared__ float xs[D_DIM];
    __shared__ float lg[E_NUM];

    // load one token row (1024 floats) and convert to fp16 on the way
    float4 v = x4[(size_t)n * (D_DIM / 4) + tid];
    ((float4*)xs)[tid] = v;
    __half2 ha = __floats2half2_rn(v.x, v.y);
    __half2 hb = __floats2half2_rn(v.z, v.w);
    uint2 o; o.x = *(uint32_t*)&ha; o.y = *(uint32_t*)&hb;
    x16[(size_t)n * (D_DIM / 4) + tid] = o;
    __syncthreads();

    int w = tid >> 5, lane = tid & 31;   // warp w -> expert w
    const float* wr = rw + (size_t)w * D_DIM;
    float s = 0.f;
    for (int i = lane; i < D_DIM; i += 32) s += xs[i] * wr[i];
    #pragma unroll
    for (int off = 16; off; off >>= 1) s += __shfl_xor_sync(0xffffffff, s, off);
    if (lane == 0) lg[w] = s;
    __syncthreads();

    if (tid == 0) {
        float l[E_NUM];
        #pragma unroll
        for (int e = 0; e < E_NUM; e++) l[e] = lg[e];

        int e0 = 0; float b0 = l[0] + rb[0];
        #pragma unroll
        for (int e = 1; e < E_NUM; e++) { float be = l[e] + rb[e]; if (be > b0) { b0 = be; e0 = e; } }
        int e1 = -1; float b1 = -1e30f;
        #pragma unroll
        for (int e = 0; e < E_NUM; e++) {
            if (e == e0) continue;
            float be = l[e] + rb[e];
            if (be > b1) { b1 = be; e1 = e; }
        }

        float l0 = l[e0], l1 = l[e1];
        float m2 = fmaxf(l0, l1);
        float w0 = expf(l0 - m2), w1 = expf(l1 - m2);
        float inv = 1.f / (w0 + w1);
        w0 *= inv; w1 *= inv;

        float mx = l[0];
        #pragma unroll
        for (int e = 1; e < E_NUM; e++) mx = fmaxf(mx, l[e]);
        float pe[E_NUM]; float se = 0.f;
        #pragma unroll
        for (int e = 0; e < E_NUM; e++) { pe[e] = expf(l[e] - mx); se += pe[e]; }
        float z = mx + logf(se);
        float invse = 1.f / se;
        g_z[n] = z;
        #pragma unroll
        for (int e = 0; e < E_NUM; e++) g_probs[n * E_NUM + e] = pe[e] * invse;

        g_topk[n * 2 + 0] = e0; g_topk[n * 2 + 1] = e1;
        g_wts[n * 2 + 0]  = w0; g_wts[n * 2 + 1]  = w1;
    }
}

// ============================ finalize + scatter (single block, parallel) ============================
__global__ __launch_bounds__(256) void finalize_scatter_kernel(
    float* __restrict__ out_scalars, int have_scalars)
{
    __shared__ int scnt[E_NUM];
    __shared__ int scur[E_NUM];
    __shared__ float red[9 * 256];
    __shared__ float sres[9];
    int tid = threadIdx.x;
    if (tid < E_NUM) scnt[tid] = 0;
    __syncthreads();

    // expert counts (integer atomics: deterministic)
    for (int i = tid; i < NK; i += 256) atomicAdd(&scnt[g_topk[i]], 1);

    // partial sums for z^2 and per-expert probs
    float pz = 0.f;
    float pp[E_NUM];
    #pragma unroll
    for (int e = 0; e < E_NUM; e++) pp[e] = 0.f;
    for (int n = tid; n < N_TOK; n += 256) {
        float z = g_z[n];
        pz += z * z;
        #pragma unroll
        for (int e = 0; e < E_NUM; e++) pp[e] += g_probs[n * E_NUM + e];
    }
    red[tid] = pz;
    #pragma unroll
    for (int e = 0; e < E_NUM; e++) red[(e + 1) * 256 + tid] = pp[e];
    __syncthreads();

    if (tid == 0) {
        int acc = 0;
        #pragma unroll
        for (int e = 0; e < E_NUM; e++) {
            g_off[e] = acc; g_cnt[e] = scnt[e]; scur[e] = acc;
            acc += scnt[e];
        }
    }
    if (tid < 9) {  // deterministic fixed-order reductions
        float s = 0.f;
        #pragma unroll 8
        for (int j = 0; j < 256; j++) s += red[tid * 256 + j];
        sres[tid] = s;
    }
    __syncthreads();

    if (tid == 0 && have_scalars) {
        float lb = 0.f;
        #pragma unroll
        for (int e = 0; e < E_NUM; e++)
            lb += (sres[e + 1] / (float)N_TOK) * ((float)scnt[e] / (float)N_TOK);
        lb *= (float)E_NUM;
        out_scalars[0] = 0.f;
        out_scalars[1] = sres[0] / (float)N_TOK * Z_COEF;
        out_scalars[2] = lb;
    }

    for (int i = tid; i < NK; i += 256) {
        int e = g_topk[i];
        int p = atomicAdd(&scur[e], 1);
        g_rowtok[p] = i >> 1;
        g_roww[p]   = g_wts[i];
        g_pos[i]    = p;
    }
}

// ============================ tensor-core GEMMs (mma.sync HMMA) ============================
// Tile: BM=128, BN=64, BK=32. 8 warps as 4(M) x 2(N); warp tile 32x32 per output.
// A (fp16 activations) via cp.async double-buffer; W (fp32 weights) via
// LDG->cvt->STS fp16, software-pipelined. smem rows padded to 40 halves (80B).
// (R5/R8 mainloop, frozen — measured at ~90% of the legacy-HMMA issue ceiling.)
#define LDR 80
#define GU_BG 10240
#define GU_BU 15360
#define GU_STG 20480
#define DN_B  10240
#define DN_STG 15360

__global__ __launch_bounds__(256) void gateup_mma(
    const float* __restrict__ GateW, const float* __restrict__ UpW,
    const float* __restrict__ ShG,   const float* __restrict__ ShU)
{
    int grp = blockIdx.z;
    bool routed = grp < E_NUM;
    int rbase = routed ? g_off[grp] : 0;
    int rcnt  = routed ? g_cnt[grp] : N_TOK;
    int m0 = blockIdx.y * 128;
    if (m0 >= rcnt) return;
    int n0 = blockIdx.x * 64;

    const float* Wg = routed ? GateW + (size_t)grp * H_DIM * D_DIM : ShG;
    const float* Wu = routed ? UpW   + (size_t)grp * H_DIM * D_DIM : ShU;
    __half* Hout = routed ? g_h16 : g_hsh16;

    __shared__ __align__(16) char smem[2 * GU_STG];
    uint32_t sb = smem_u32(smem);
    int tid = threadIdx.x;

    int rA0 = tid >> 2, rA1 = rA0 + 64, seg = tid & 3;
    const __half *asrc0 = g_x16, *asrc1 = g_x16;
    uint32_t av0 = 0, av1 = 0;
    if (m0 + rA0 < rcnt) {
        int tk = routed ? g_rowtok[rbase + m0 + rA0] : m0 + rA0;
        asrc0 = g_x16 + (size_t)tk * D_DIM + seg * 8; av0 = 16;
    }
    if (m0 + rA1 < rcnt) {
        int tk = routed ? g_rowtok[rbase + m0 + rA1] : m0 + rA1;
        asrc1 = g_x16 + (size_t)tk * D_DIM + seg * 8; av1 = 16;
    }
    const float* gw = Wg + (size_t)(n0 + rA0) * D_DIM + seg * 8;
    const float* uw = Wu + (size_t)(n0 + rA0) * D_DIM + seg * 8;

    uint32_t dA0 = sb + rA0 * LDR + seg * 16;
    uint32_t dA1 = sb + rA1 * LDR + seg * 16;
    uint32_t dG  = sb + GU_BG + rA0 * LDR + seg * 16;
    uint32_t dU  = sb + GU_BU + rA0 * LDR + seg * 16;

    float4 wg0, wg1, wu0, wu1;
    auto ldg_w = [&](int s) {
        const float4* gp = (const float4*)(gw + s * 32);
        const float4* up = (const float4*)(uw + s * 32);
        wg0 = gp[0]; wg1 = gp[1];
        wu0 = up[0]; wu1 = up[1];
    };
    auto sts_w = [&](int buf) {
        uint32_t o = (uint32_t)buf * GU_STG;
        *(uint4*)(smem + (dG + o - sb)) = pack8(wg0, wg1);
        *(uint4*)(smem + (dU + o - sb)) = pack8(wu0, wu1);
    };
    auto cp_a = [&](int s) {
        uint32_t o = (uint32_t)(s & 1) * GU_STG;
        cp16(dA0 + o, asrc0 + s * 32, av0);
        cp16(dA1 + o, asrc1 + s * 32, av1);
        cp_commit();
    };

    const int S = D_DIM / 32;
    ldg_w(0); sts_w(0); cp_a(0);
    ldg_w(1); cp_a(1);

    int warp = tid >> 5, lane = tid & 31;
    int wm = warp & 3, wn = warp >> 2;
    int g = lane >> 3;
    int brow = ((g >> 1) << 3) + (lane & 7);
    int bks = (g & 1) << 4;

    float cg[2][4][4] = {}, cu[2][4][4] = {};

    #pragma unroll 1
    for (int s = 0; s < S; s++) {
        if (s + 1 < S) CP_WAIT(1);
        else           CP_WAIT(0);
        __syncthreads();
        uint32_t o = sb + (uint32_t)(s & 1) * GU_STG;

        uint32_t a[2][2][4];
        #pragma unroll
        for (int mt = 0; mt < 2; mt++)
            #pragma unroll
            for (int kt = 0; kt < 2; kt++)
                ldsm4(a[mt][kt], o + (wm * 32 + mt * 16 + (lane & 15)) * LDR + kt * 32 + (lane >> 4) * 16);

        uint32_t bg[2][2][4], bu[2][2][4];
        #pragma unroll
        for (int nt = 0; nt < 2; nt++)
            #pragma unroll
            for (int kt = 0; kt < 2; kt++) {
                uint32_t ro = (wn * 32 + nt * 16 + brow) * LDR + kt * 32 + bks;
                ldsm4(bg[nt][kt], o + GU_BG + ro);
                ldsm4(bu[nt][kt], o + GU_BU + ro);
            }

        #pragma unroll
        for (int mt = 0; mt < 2; mt++)
            #pragma unroll
            for (int nt = 0; nt < 2; nt++)
                #pragma unroll
                for (int kt = 0; kt < 2; kt++) {
                    mma16816(cg[mt][nt * 2 + 0], a[mt][kt], &bg[nt][kt][0]);
                    mma16816(cg[mt][nt * 2 + 1], a[mt][kt], &bg[nt][kt][2]);
                    mma16816(cu[mt][nt * 2 + 0], a[mt][kt], &bu[nt][kt][0]);
                    mma16816(cu[mt][nt * 2 + 1], a[mt][kt], &bu[nt][kt][2]);
                }

        if (s + 1 < S) sts_w((s + 1) & 1);
        __syncthreads();
        if (s + 2 < S) { cp_a(s + 2); ldg_w(s + 2); }
    }

    #pragma unroll
    for (int mt = 0; mt < 2; mt++) {
        int rbaserow = m0 + wm * 32 + mt * 16 + (lane >> 2);
        #pragma unroll
        for (int h = 0; h < 2; h++) {
            int r = rbaserow + h * 8;
            if (r >= rcnt) continue;
            __half* hp = Hout + (size_t)(rbase + r) * H_DIM + n0 + wn * 32 + (lane & 3) * 2;
            #pragma unroll
            for (int j = 0; j < 4; j++) {
                float g0 = cg[mt][j][h * 2 + 0], g1 = cg[mt][j][h * 2 + 1];
                float u0 = cu[mt][j][h * 2 + 0], u1 = cu[mt][j][h * 2 + 1];
                float h0 = g0 * u0 / (1.f + __expf(-g0));
                float h1 = g1 * u1 / (1.f + __expf(-g1));
                *(__half2*)(hp + j * 8) = __floats2half2_rn(h0, h1);
            }
        }
    }
}

__global__ __launch_bounds__(256, 2) void down_mma(
    const float* __restrict__ DownW, const float* __restrict__ ShD,
    float* __restrict__ Out)
{
    int grp = blockIdx.z;
    bool routed = grp < E_NUM;
    int rbase = routed ? g_off[grp] : 0;
    int rcnt  = routed ? g_cnt[grp] : N_TOK;
    int m0 = blockIdx.y * 128;
    if (m0 >= rcnt) return;
    int n0 = blockIdx.x * 64;

    const float* Wd  = routed ? DownW + (size_t)grp * D_DIM * H_DIM : ShD;
    const __half* Hin = routed ? g_h16 : g_hsh16;

    __shared__ __align__(16) char smem[2 * DN_STG];
    uint32_t sb = smem_u32(smem);
    int tid = threadIdx.x;

    int rA0 = tid >> 2, rA1 = rA0 + 64, seg = tid & 3;
    const __half *asrc0 = Hin, *asrc1 = Hin;
    uint32_t av0 = 0, av1 = 0;
    if (m0 + rA0 < rcnt) { asrc0 = Hin + (size_t)(rbase + m0 + rA0) * H_DIM + seg * 8; av0 = 16; }
    if (m0 + rA1 < rcnt) { asrc1 = Hin + (size_t)(rbase + m0 + rA1) * H_DIM + seg * 8; av1 = 16; }
    const float* dw = Wd + (size_t)(n0 + rA0) * H_DIM + seg * 8;

    uint32_t dA0 = sb + rA0 * LDR + seg * 16;
    uint32_t dA1 = sb + rA1 * LDR + seg * 16;
    uint32_t dB  = sb + DN_B + rA0 * LDR + seg * 16;

    float4 wd0, wd1;
    auto ldg_w = [&](int s) {
        const float4* p = (const float4*)(dw + s * 32);
        wd0 = p[0]; wd1 = p[1];
    };
    auto sts_w = [&](int buf) {
        *(uint4*)(smem + (dB + (uint32_t)buf * DN_STG - sb)) = pack8(wd0, wd1);
    };
    auto cp_a = [&](int s) {
        uint32_t o = (uint32_t)(s & 1) * DN_STG;
        cp16(dA0 + o, asrc0 + s * 32, av0);
        cp16(dA1 + o, asrc1 + s * 32, av1);
        cp_commit();
    };

    const int S = H_DIM / 32;
    ldg_w(0); sts_w(0); cp_a(0);
    ldg_w(1); cp_a(1);

    int warp = tid >> 5, lane = tid & 31;
    int wm = warp & 3, wn = warp >> 2;
    int g = lane >> 3;
    int brow = ((g >> 1) << 3) + (lane & 7);
    int bks = (g & 1) << 4;

    float c[2][4][4] = {};

    #pragma unroll 1
    for (int s = 0; s < S; s++) {
        if (s + 1 < S) CP_WAIT(1);
        else           CP_WAIT(0);
        __syncthreads();
        uint32_t o = sb + (uint32_t)(s & 1) * DN_STG;

        uint32_t a[2][2][4];
        #pragma unroll
        for (int mt = 0; mt < 2; mt++)
            #pragma unroll
            for (int kt = 0; kt < 2; kt++)
                ldsm4(a[mt][kt], o + (wm * 32 + mt * 16 + (lane & 15)) * LDR + kt * 32 + (lane >> 4) * 16);

        uint32_t b[2][2][4];
        #pragma unroll
        for (int nt = 0; nt < 2; nt++)
            #pragma unroll
            for (int kt = 0; kt < 2; kt++)
                ldsm4(b[nt][kt], o + DN_B + (wn * 32 + nt * 16 + brow) * LDR + kt * 32 + bks);

        #pragma unroll
        for (int mt = 0; mt < 2; mt++)
            #pragma unroll
            for (int nt = 0; nt < 2; nt++)
                #pragma unroll
                for (int kt = 0; kt < 2; kt++) {
                    mma16816(c[mt][nt * 2 + 0], a[mt][kt], &b[nt][kt][0]);
                    mma16816(c[mt][nt * 2 + 1], a[mt][kt], &b[nt][kt][2]);
                }

        if (s + 1 < S) sts_w((s + 1) & 1);
        __syncthreads();
        if (s + 2 < S) { cp_a(s + 2); ldg_w(s + 2); }
    }

    #pragma unroll
    for (int mt = 0; mt < 2; mt++) {
        int rbaserow = m0 + wm * 32 + mt * 16 + (lane >> 2);
        #pragma unroll
        for (int h = 0; h < 2; h++) {
            int r = rbaserow + h * 8;
            if (r >= rcnt) continue;
            float w = routed ? g_roww[rbase + r] : 1.f;
            float* op = (routed ? g_pairout + (size_t)(rbase + r) * D_DIM
                                : Out + (size_t)r * D_DIM)
                        + n0 + wn * 32 + (lane & 3) * 2;
            #pragma unroll
            for (int j = 0; j < 4; j++) {
                float2 v = make_float2(c[mt][j][h * 2 + 0] * w, c[mt][j][h * 2 + 1] * w);
                *(float2*)(op + j * 8) = v;
            }
        }
    }
}

// ============================ combine ============================
__global__ void combine_kernel(float* __restrict__ out) {
    int i4 = blockIdx.x * 256 + threadIdx.x;
    const int total4 = N_TOK * D_DIM / 4;
    if (i4 >= total4) return;
    int n  = i4 / (D_DIM / 4);
    int d4 = i4 % (D_DIM / 4);
    int p0 = g_pos[n * 2 + 0];
    int p1 = g_pos[n * 2 + 1];
    const float4* pr = (const float4*)g_pairout;
    float4 o = ((float4*)out)[i4];
    float4 a = pr[(size_t)p0 * (D_DIM / 4) + d4];
    float4 b = pr[(size_t)p1 * (D_DIM / 4) + d4];
    o.x += a.x + b.x; o.y += a.y + b.y; o.z += a.z + b.z; o.w += a.w + b.w;
    ((float4*)out)[i4] = o;
}

// ============================ launch ============================
extern "C" void kernel_launch(void* const* d_in, const int* in_sizes, int n_in,
                              void* d_out, int out_size) {
    const float* x      = (const float*)d_in[0];
    const float* rw     = (const float*)d_in[1];
    const float* rb     = (const float*)d_in[2];
    const float* gate_w = (const float*)d_in[3];
    const float* up_w   = (const float*)d_in[4];
    const float* down_w = (const float*)d_in[5];
    const float* shg    = (const float*)d_in[6];
    const float* shu    = (const float*)d_in[7];
    const float* shd    = (const float*)d_in[8];
    float* out = (float*)d_out;

    const int hid_elems = N_TOK * D_DIM;
    int have_scalars = (out_size >= hid_elems + 3) ? 1 : 0;

    void* p_x16;
    cudaGetSymbolAddress(&p_x16, g_x16);

    router_convert_kernel<<<N_TOK, 256>>>((const float4*)x, rw, rb, (uint2*)p_x16);
    finalize_scatter_kernel<<<1, 256>>>(out + hid_elems, have_scalars);

    gateup_mma<<<dim3(H_DIM / 64, 16, 9), 256>>>(gate_w, up_w, shg, shu);
    down_mma<<<dim3(D_DIM / 64, 16, 9), 256>>>(down_w, shd, out);

    combine_kernel<<<(N_TOK * D_DIM / 4 + 255) / 256, 256>>>(out);
}

// round 11
// speedup vs baseline: 1.2629x; 1.0104x over previous
#include <cuda_runtime.h>
#include <cuda_fp16.h>
#include <math.h>
#include <stdint.h>

#define N_TOK 2048
#define D_DIM 1024
#define E_NUM 8
#define K_TOP 2
#define H_DIM 2048
#define NK (N_TOK*K_TOP)
#define Z_COEF 1e-4f

// ---------------- fp16 scratch (device globals; no allocs allowed) ----------------
__device__ __half g_x16[(size_t)N_TOK*D_DIM];
__device__ __half g_h16[(size_t)NK*H_DIM];
__device__ __half g_hsh16[(size_t)N_TOK*H_DIM];
__device__ float  g_pairout[(size_t)NK*D_DIM];

// ---------------- router scratch ----------------
__device__ int   g_topk[NK];
__device__ float g_wts[NK];
__device__ float g_probs[(size_t)N_TOK*E_NUM];
__device__ float g_z[N_TOK];
__device__ int   g_cnt[E_NUM];
__device__ int   g_off[E_NUM];
__device__ int   g_rowtok[NK];
__device__ float g_roww[NK];
__device__ int   g_pos[NK];

// ============================ PTX helpers ============================
__device__ __forceinline__ uint32_t smem_u32(const void* p){
    uint32_t a;
    asm("{ .reg .u64 t; cvta.to.shared.u64 t, %1; cvt.u32.u64 %0, t; }" : "=r"(a) : "l"(p));
    return a;
}
__device__ __forceinline__ void cp16(uint32_t dst, const void* src, uint32_t sz){
    asm volatile("cp.async.cg.shared.global [%0], [%1], 16, %2;"
                 :: "r"(dst), "l"(src), "r"(sz) : "memory");
}
__device__ __forceinline__ void cp_commit(){ asm volatile("cp.async.commit_group;" ::: "memory"); }
__device__ __forceinline__ void ldsm4(uint32_t* r, uint32_t addr){
    asm volatile("ldmatrix.sync.aligned.m8n8.x4.shared.b16 {%0,%1,%2,%3}, [%4];"
                 : "=r"(r[0]), "=r"(r[1]), "=r"(r[2]), "=r"(r[3]) : "r"(addr));
}
__device__ __forceinline__ void mma16816(float* c, const uint32_t* a, const uint32_t* b){
    asm volatile("mma.sync.aligned.m16n8k16.row.col.f32.f16.f16.f32 "
                 "{%0,%1,%2,%3}, {%4,%5,%6,%7}, {%8,%9}, {%0,%1,%2,%3};"
                 : "+f"(c[0]), "+f"(c[1]), "+f"(c[2]), "+f"(c[3])
                 : "r"(a[0]), "r"(a[1]), "r"(a[2]), "r"(a[3]), "r"(b[0]), "r"(b[1]));
}
#define CP_WAIT(N) asm volatile("cp.async.wait_group %0;" :: "n"(N) : "memory")

__device__ __forceinline__ uint4 pack8(const float4 a, const float4 b){
    uint4 v;
    __half2 h0 = __floats2half2_rn(a.x, a.y);
    __half2 h1 = __floats2half2_rn(a.z, a.w);
    __half2 h2 = __floats2half2_rn(b.x, b.y);
    __half2 h3 = __floats2half2_rn(b.z, b.w);
    v.x = *(uint32_t*)&h0; v.y = *(uint32_t*)&h1;
    v.z = *(uint32_t*)&h2; v.w = *(uint32_t*)&h3;
    return v;
}

// ============================ router + x convert (fused, atomic-free) ============================
__global__ __launch_bounds__(256) void router_convert_kernel(
    const float4* __restrict__ x4, const float* __restrict__ rw,
    const float* __restrict__ rb,  uint2* __restrict__ x16)
{
    int n = blockIdx.x;
    int tid = threadIdx.x;
    __shared__ float xs[D_DIM];
    __shared__ float lg[E_NUM];

    float4 v = x4[(size_t)n * (D_DIM / 4) + tid];
    ((float4*)xs)[tid] = v;
    __half2 ha = __floats2half2_rn(v.x, v.y);
    __half2 hb = __floats2half2_rn(v.z, v.w);
    uint2 o; o.x = *(uint32_t*)&ha; o.y = *(uint32_t*)&hb;
    x16[(size_t)n * (D_DIM / 4) + tid] = o;
    __syncthreads();

    int w = tid >> 5, lane = tid & 31;
    const float* wr = rw + (size_t)w * D_DIM;
    float s = 0.f;
    for (int i = lane; i < D_DIM; i += 32) s += xs[i] * wr[i];
    #pragma unroll
    for (int off = 16; off; off >>= 1) s += __shfl_xor_sync(0xffffffff, s, off);
    if (lane == 0) lg[w] = s;
    __syncthreads();

    if (tid == 0) {
        float l[E_NUM];
        #pragma unroll
        for (int e = 0; e < E_NUM; e++) l[e] = lg[e];

        int e0 = 0; float b0 = l[0] + rb[0];
        #pragma unroll
        for (int e = 1; e < E_NUM; e++) { float be = l[e] + rb[e]; if (be > b0) { b0 = be; e0 = e; } }
        int e1 = -1; float b1 = -1e30f;
        #pragma unroll
        for (int e = 0; e < E_NUM; e++) {
            if (e == e0) continue;
            float be = l[e] + rb[e];
            if (be > b1) { b1 = be; e1 = e; }
        }

        float l0 = l[e0], l1 = l[e1];
        float m2 = fmaxf(l0, l1);
        float w0 = expf(l0 - m2), w1 = expf(l1 - m2);
        float inv = 1.f / (w0 + w1);
        w0 *= inv; w1 *= inv;

        float mx = l[0];
        #pragma unroll
        for (int e = 1; e < E_NUM; e++) mx = fmaxf(mx, l[e]);
        float pe[E_NUM]; float se = 0.f;
        #pragma unroll
        for (int e = 0; e < E_NUM; e++) { pe[e] = expf(l[e] - mx); se += pe[e]; }
        float z = mx + logf(se);
        float invse = 1.f / se;
        g_z[n] = z;
        #pragma unroll
        for (int e = 0; e < E_NUM; e++) g_probs[n * E_NUM + e] = pe[e] * invse;

        g_topk[n * 2 + 0] = e0; g_topk[n * 2 + 1] = e1;
        g_wts[n * 2 + 0]  = w0; g_wts[n * 2 + 1]  = w1;
    }
}

// ============================ finalize + scatter (single block, parallel) ============================
__global__ __launch_bounds__(256) void finalize_scatter_kernel(
    float* __restrict__ out_scalars, int have_scalars)
{
    __shared__ int scnt[E_NUM];
    __shared__ int scur[E_NUM];
    __shared__ float red[9 * 256];
    __shared__ float sres[9];
    int tid = threadIdx.x;
    if (tid < E_NUM) scnt[tid] = 0;
    __syncthreads();

    for (int i = tid; i < NK; i += 256) atomicAdd(&scnt[g_topk[i]], 1);

    float pz = 0.f;
    float pp[E_NUM];
    #pragma unroll
    for (int e = 0; e < E_NUM; e++) pp[e] = 0.f;
    for (int n = tid; n < N_TOK; n += 256) {
        float z = g_z[n];
        pz += z * z;
        #pragma unroll
        for (int e = 0; e < E_NUM; e++) pp[e] += g_probs[n * E_NUM + e];
    }
    red[tid] = pz;
    #pragma unroll
    for (int e = 0; e < E_NUM; e++) red[(e + 1) * 256 + tid] = pp[e];
    __syncthreads();

    if (tid == 0) {
        int acc = 0;
        #pragma unroll
        for (int e = 0; e < E_NUM; e++) {
            g_off[e] = acc; g_cnt[e] = scnt[e]; scur[e] = acc;
            acc += scnt[e];
        }
    }
    if (tid < 9) {
        float s = 0.f;
        #pragma unroll 8
        for (int j = 0; j < 256; j++) s += red[tid * 256 + j];
        sres[tid] = s;
    }
    __syncthreads();

    if (tid == 0 && have_scalars) {
        float lb = 0.f;
        #pragma unroll
        for (int e = 0; e < E_NUM; e++)
            lb += (sres[e + 1] / (float)N_TOK) * ((float)scnt[e] / (float)N_TOK);
        lb *= (float)E_NUM;
        out_scalars[0] = 0.f;
        out_scalars[1] = sres[0] / (float)N_TOK * Z_COEF;
        out_scalars[2] = lb;
    }

    for (int i = tid; i < NK; i += 256) {
        int e = g_topk[i];
        int p = atomicAdd(&scur[e], 1);
        g_rowtok[p] = i >> 1;
        g_roww[p]   = g_wts[i];
        g_pos[i]    = p;
    }
}

// ============================ tensor-core GEMMs (mma.sync HMMA) ============================
// BM=128, BK=32, 8 warps 4(M)x2(N), warp tile 32x32 per B matrix; both kernels
// process TWO 64-row B panels per stage (gate+up / down lo+hi halves) so every
// stage issues 32 mma/warp against the fixed per-stage costs.
#define LDR 80
#define GU_BG 10240
#define GU_BU 15360
#define GU_STG 20480
// down uses identical layout/sizes

__global__ __launch_bounds__(256) void gateup_mma(
    const float* __restrict__ GateW, const float* __restrict__ UpW,
    const float* __restrict__ ShG,   const float* __restrict__ ShU)
{
    int grp = blockIdx.z;
    bool routed = grp < E_NUM;
    int rbase = routed ? g_off[grp] : 0;
    int rcnt  = routed ? g_cnt[grp] : N_TOK;
    int m0 = blockIdx.y * 128;
    if (m0 >= rcnt) return;
    int n0 = blockIdx.x * 64;

    const float* Wg = routed ? GateW + (size_t)grp * H_DIM * D_DIM : ShG;
    const float* Wu = routed ? UpW   + (size_t)grp * H_DIM * D_DIM : ShU;
    __half* Hout = routed ? g_h16 : g_hsh16;

    __shared__ __align__(16) char smem[2 * GU_STG];
    uint32_t sb = smem_u32(smem);
    int tid = threadIdx.x;

    int rA0 = tid >> 2, rA1 = rA0 + 64, seg = tid & 3;
    const __half *asrc0 = g_x16, *asrc1 = g_x16;
    uint32_t av0 = 0, av1 = 0;
    if (m0 + rA0 < rcnt) {
        int tk = routed ? g_rowtok[rbase + m0 + rA0] : m0 + rA0;
        asrc0 = g_x16 + (size_t)tk * D_DIM + seg * 8; av0 = 16;
    }
    if (m0 + rA1 < rcnt) {
        int tk = routed ? g_rowtok[rbase + m0 + rA1] : m0 + rA1;
        asrc1 = g_x16 + (size_t)tk * D_DIM + seg * 8; av1 = 16;
    }
    const float* gw = Wg + (size_t)(n0 + rA0) * D_DIM + seg * 8;
    const float* uw = Wu + (size_t)(n0 + rA0) * D_DIM + seg * 8;

    uint32_t dA0 = sb + rA0 * LDR + seg * 16;
    uint32_t dA1 = sb + rA1 * LDR + seg * 16;
    uint32_t dG  = sb + GU_BG + rA0 * LDR + seg * 16;
    uint32_t dU  = sb + GU_BU + rA0 * LDR + seg * 16;

    float4 wg0, wg1, wu0, wu1;
    auto ldg_w = [&](int s) {
        const float4* gp = (const float4*)(gw + s * 32);
        const float4* up = (const float4*)(uw + s * 32);
        wg0 = gp[0]; wg1 = gp[1];
        wu0 = up[0]; wu1 = up[1];
    };
    auto sts_w = [&](int buf) {
        uint32_t o = (uint32_t)buf * GU_STG;
        *(uint4*)(smem + (dG + o - sb)) = pack8(wg0, wg1);
        *(uint4*)(smem + (dU + o - sb)) = pack8(wu0, wu1);
    };
    auto cp_a = [&](int s) {
        uint32_t o = (uint32_t)(s & 1) * GU_STG;
        cp16(dA0 + o, asrc0 + s * 32, av0);
        cp16(dA1 + o, asrc1 + s * 32, av1);
        cp_commit();
    };

    const int S = D_DIM / 32;
    ldg_w(0); sts_w(0); cp_a(0);
    ldg_w(1); cp_a(1);

    int warp = tid >> 5, lane = tid & 31;
    int wm = warp & 3, wn = warp >> 2;
    int g = lane >> 3;
    int brow = ((g >> 1) << 3) + (lane & 7);
    int bks = (g & 1) << 4;

    float cg[2][4][4] = {}, cu[2][4][4] = {};

    #pragma unroll 1
    for (int s = 0; s < S; s++) {
        if (s + 1 < S) CP_WAIT(1);
        else           CP_WAIT(0);
        __syncthreads();
        uint32_t o = sb + (uint32_t)(s & 1) * GU_STG;

        uint32_t a[2][2][4];
        #pragma unroll
        for (int mt = 0; mt < 2; mt++)
            #pragma unroll
            for (int kt = 0; kt < 2; kt++)
                ldsm4(a[mt][kt], o + (wm * 32 + mt * 16 + (lane & 15)) * LDR + kt * 32 + (lane >> 4) * 16);

        uint32_t bg[2][2][4], bu[2][2][4];
        #pragma unroll
        for (int nt = 0; nt < 2; nt++)
            #pragma unroll
            for (int kt = 0; kt < 2; kt++) {
                uint32_t ro = (wn * 32 + nt * 16 + brow) * LDR + kt * 32 + bks;
                ldsm4(bg[nt][kt], o + GU_BG + ro);
                ldsm4(bu[nt][kt], o + GU_BU + ro);
            }

        #pragma unroll
        for (int mt = 0; mt < 2; mt++)
            #pragma unroll
            for (int nt = 0; nt < 2; nt++)
                #pragma unroll
                for (int kt = 0; kt < 2; kt++) {
                    mma16816(cg[mt][nt * 2 + 0], a[mt][kt], &bg[nt][kt][0]);
                    mma16816(cg[mt][nt * 2 + 1], a[mt][kt], &bg[nt][kt][2]);
                    mma16816(cu[mt][nt * 2 + 0], a[mt][kt], &bu[nt][kt][0]);
                    mma16816(cu[mt][nt * 2 + 1], a[mt][kt], &bu[nt][kt][2]);
                }

        if (s + 1 < S) sts_w((s + 1) & 1);
        __syncthreads();
        if (s + 2 < S) { cp_a(s + 2); ldg_w(s + 2); }
    }

    #pragma unroll
    for (int mt = 0; mt < 2; mt++) {
        int rbaserow = m0 + wm * 32 + mt * 16 + (lane >> 2);
        #pragma unroll
        for (int h = 0; h < 2; h++) {
            int r = rbaserow + h * 8;
            if (r >= rcnt) continue;
            __half* hp = Hout + (size_t)(rbase + r) * H_DIM + n0 + wn * 32 + (lane & 3) * 2;
            #pragma unroll
            for (int j = 0; j < 4; j++) {
                float g0 = cg[mt][j][h * 2 + 0], g1 = cg[mt][j][h * 2 + 1];
                float u0 = cu[mt][j][h * 2 + 0], u1 = cu[mt][j][h * 2 + 1];
                float h0 = g0 * u0 / (1.f + __expf(-g0));
                float h1 = g1 * u1 / (1.f + __expf(-g1));
                *(__half2*)(hp + j * 8) = __floats2half2_rn(h0, h1);
            }
        }
    }
}

// down: BN=128 via two 64-row panels of Wd (cols [n0,n0+64) and [n0+64,n0+128))
__global__ __launch_bounds__(256) void down_mma(
    const float* __restrict__ DownW, const float* __restrict__ ShD,
    float* __restrict__ Out)
{
    int grp = blockIdx.z;
    bool routed = grp < E_NUM;
    int rbase = routed ? g_off[grp] : 0;
    int rcnt  = routed ? g_cnt[grp] : N_TOK;
    int m0 = blockIdx.y * 128;
    if (m0 >= rcnt) return;
    int n0 = blockIdx.x * 128;

    const float* Wd  = routed ? DownW + (size_t)grp * D_DIM * H_DIM : ShD;
    const __half* Hin = routed ? g_h16 : g_hsh16;

    __shared__ __align__(16) char smem[2 * GU_STG];
    uint32_t sb = smem_u32(smem);
    int tid = threadIdx.x;

    int rA0 = tid >> 2, rA1 = rA0 + 64, seg = tid & 3;
    const __half *asrc0 = Hin, *asrc1 = Hin;
    uint32_t av0 = 0, av1 = 0;
    if (m0 + rA0 < rcnt) { asrc0 = Hin + (size_t)(rbase + m0 + rA0) * H_DIM + seg * 8; av0 = 16; }
    if (m0 + rA1 < rcnt) { asrc1 = Hin + (size_t)(rbase + m0 + rA1) * H_DIM + seg * 8; av1 = 16; }
    const float* lw = Wd + (size_t)(n0 + rA0) * H_DIM + seg * 8;        // cols [n0, n0+64)
    const float* hw = Wd + (size_t)(n0 + 64 + rA0) * H_DIM + seg * 8;   // cols [n0+64, n0+128)

    uint32_t dA0 = sb + rA0 * LDR + seg * 16;
    uint32_t dA1 = sb + rA1 * LDR + seg * 16;
    uint32_t dL  = sb + GU_BG + rA0 * LDR + seg * 16;
    uint32_t dH  = sb + GU_BU + rA0 * LDR + seg * 16;

    float4 wl0, wl1, wh0, wh1;
    auto ldg_w = [&](int s) {
        const float4* lp = (const float4*)(lw + s * 32);
        const float4* hp = (const float4*)(hw + s * 32);
        wl0 = lp[0]; wl1 = lp[1];
        wh0 = hp[0]; wh1 = hp[1];
    };
    auto sts_w = [&](int buf) {
        uint32_t o = (uint32_t)buf * GU_STG;
        *(uint4*)(smem + (dL + o - sb)) = pack8(wl0, wl1);
        *(uint4*)(smem + (dH + o - sb)) = pack8(wh0, wh1);
    };
    auto cp_a = [&](int s) {
        uint32_t o = (uint32_t)(s & 1) * GU_STG;
        cp16(dA0 + o, asrc0 + s * 32, av0);
        cp16(dA1 + o, asrc1 + s * 32, av1);
        cp_commit();
    };

    const int S = H_DIM / 32;
    ldg_w(0); sts_w(0); cp_a(0);
    ldg_w(1); cp_a(1);

    int warp = tid >> 5, lane = tid & 31;
    int wm = warp & 3, wn = warp >> 2;
    int g = lane >> 3;
    int brow = ((g >> 1) << 3) + (lane & 7);
    int bks = (g & 1) << 4;

    float cl[2][4][4] = {}, ch[2][4][4] = {};

    #pragma unroll 1
    for (int s = 0; s < S; s++) {
        if (s + 1 < S) CP_WAIT(1);
        else           CP_WAIT(0);
        __syncthreads();
        uint32_t o = sb + (uint32_t)(s & 1) * GU_STG;

        uint32_t a[2][2][4];
        #pragma unroll
        for (int mt = 0; mt < 2; mt++)
            #pragma unroll
            for (int kt = 0; kt < 2; kt++)
                ldsm4(a[mt][kt], o + (wm * 32 + mt * 16 + (lane & 15)) * LDR + kt * 32 + (lane >> 4) * 16);

        uint32_t bl[2][2][4], bh[2][2][4];
        #pragma unroll
        for (int nt = 0; nt < 2; nt++)
            #pragma unroll
            for (int kt = 0; kt < 2; kt++) {
                uint32_t ro = (wn * 32 + nt * 16 + brow) * LDR + kt * 32 + bks;
                ldsm4(bl[nt][kt], o + GU_BG + ro);
                ldsm4(bh[nt][kt], o + GU_BU + ro);
            }

        #pragma unroll
        for (int mt = 0; mt < 2; mt++)
            #pragma unroll
            for (int nt = 0; nt < 2; nt++)
                #pragma unroll
                for (int kt = 0; kt < 2; kt++) {
                    mma16816(cl[mt][nt * 2 + 0], a[mt][kt], &bl[nt][kt][0]);
                    mma16816(cl[mt][nt * 2 + 1], a[mt][kt], &bl[nt][kt][2]);
                    mma16816(ch[mt][nt * 2 + 0], a[mt][kt], &bh[nt][kt][0]);
                    mma16816(ch[mt][nt * 2 + 1], a[mt][kt], &bh[nt][kt][2]);
                }

        if (s + 1 < S) sts_w((s + 1) & 1);
        __syncthreads();
        if (s + 2 < S) { cp_a(s + 2); ldg_w(s + 2); }
    }

    #pragma unroll
    for (int mt = 0; mt < 2; mt++) {
        int rbaserow = m0 + wm * 32 + mt * 16 + (lane >> 2);
        #pragma unroll
        for (int h = 0; h < 2; h++) {
            int r = rbaserow + h * 8;
            if (r >= rcnt) continue;
            float w = routed ? g_roww[rbase + r] : 1.f;
            float* op = (routed ? g_pairout + (size_t)(rbase + r) * D_DIM
                                : Out + (size_t)r * D_DIM)
                        + n0 + wn * 32 + (lane & 3) * 2;
            #pragma unroll
            for (int j = 0; j < 4; j++) {
                float2 v0 = make_float2(cl[mt][j][h * 2 + 0] * w, cl[mt][j][h * 2 + 1] * w);
                float2 v1 = make_float2(ch[mt][j][h * 2 + 0] * w, ch[mt][j][h * 2 + 1] * w);
                *(float2*)(op + j * 8)      = v0;
                *(float2*)(op + 64 + j * 8) = v1;
            }
        }
    }
}

// ============================ combine ============================
__global__ void combine_kernel(float* __restrict__ out) {
    int i4 = blockIdx.x * 256 + threadIdx.x;
    const int total4 = N_TOK * D_DIM / 4;
    if (i4 >= total4) return;
    int n  = i4 / (D_DIM / 4);
    int d4 = i4 % (D_DIM / 4);
    int p0 = g_pos[n * 2 + 0];
    int p1 = g_pos[n * 2 + 1];
    const float4* pr = (const float4*)g_pairout;
    float4 o = ((float4*)out)[i4];
    float4 a = pr[(size_t)p0 * (D_DIM / 4) + d4];
    float4 b = pr[(size_t)p1 * (D_DIM / 4) + d4];
    o.x += a.x + b.x; o.y += a.y + b.y; o.z += a.z + b.z; o.w += a.w + b.w;
    ((float4*)out)[i4] = o;
}

// ============================ launch ============================
extern "C" void kernel_launch(void* const* d_in, const int* in_sizes, int n_in,
                              void* d_out, int out_size) {
    const float* x      = (const float*)d_in[0];
    const float* rw     = (const float*)d_in[1];
    const float* rb     = (const float*)d_in[2];
    const float* gate_w = (const float*)d_in[3];
    const float* up_w   = (const float*)d_in[4];
    const float* down_w = (const float*)d_in[5];
    const float* shg    = (const float*)d_in[6];
    const float* shu    = (const float*)d_in[7];
    const float* shd    = (const float*)d_in[8];
    float* out = (float*)d_out;

    const int hid_elems = N_TOK * D_DIM;
    int have_scalars = (out_size >= hid_elems + 3) ? 1 : 0;

    void* p_x16;
    cudaGetSymbolAddress(&p_x16, g_x16);

    router_convert_kernel<<<N_TOK, 256>>>((const float4*)x, rw, rb, (uint2*)p_x16);
    finalize_scatter_kernel<<<1, 256>>>(out + hid_elems, have_scalars);

    gateup_mma<<<dim3(H_DIM / 64, 16, 9), 256>>>(gate_w, up_w, shg, shu);
    down_mma<<<dim3(D_DIM / 128, 16, 9), 256>>>(down_w, shd, out);

    combine_kernel<<<(N_TOK * D_DIM / 4 + 255) / 256, 256>>>(out);
}

// round 12
// speedup vs baseline: 1.2632x; 1.0002x over previous
#include <cuda_runtime.h>
#include <cuda_fp16.h>
#include <math.h>
#include <stdint.h>

#define N_TOK 2048
#define D_DIM 1024
#define E_NUM 8
#define K_TOP 2
#define H_DIM 2048
#define NK (N_TOK*K_TOP)
#define Z_COEF 1e-4f

// ---------------- fp16 scratch (device globals; no allocs allowed) ----------------
__device__ __half g_x16[(size_t)N_TOK*D_DIM];
__device__ __half g_h16[(size_t)NK*H_DIM];
__device__ __half g_hsh16[(size_t)N_TOK*H_DIM];

// ---------------- router scratch ----------------
__device__ int   g_topk[NK];
__device__ float g_wts[NK];
__device__ float g_probs[(size_t)N_TOK*E_NUM];
__device__ float g_z[N_TOK];
__device__ int   g_cnt[E_NUM];
__device__ int   g_off[E_NUM];
__device__ int   g_rowtok[NK];
__device__ float g_roww[NK];

// ============================ PTX helpers ============================
__device__ __forceinline__ uint32_t smem_u32(const void* p){
    uint32_t a;
    asm("{ .reg .u64 t; cvta.to.shared.u64 t, %1; cvt.u32.u64 %0, t; }" : "=r"(a) : "l"(p));
    return a;
}
__device__ __forceinline__ void cp16(uint32_t dst, const void* src, uint32_t sz){
    asm volatile("cp.async.cg.shared.global [%0], [%1], 16, %2;"
                 :: "r"(dst), "l"(src), "r"(sz) : "memory");
}
__device__ __forceinline__ void cp_commit(){ asm volatile("cp.async.commit_group;" ::: "memory"); }
__device__ __forceinline__ void ldsm4(uint32_t* r, uint32_t addr){
    asm volatile("ldmatrix.sync.aligned.m8n8.x4.shared.b16 {%0,%1,%2,%3}, [%4];"
                 : "=r"(r[0]), "=r"(r[1]), "=r"(r[2]), "=r"(r[3]) : "r"(addr));
}
__device__ __forceinline__ void mma16816(float* c, const uint32_t* a, const uint32_t* b){
    asm volatile("mma.sync.aligned.m16n8k16.row.col.f32.f16.f16.f32 "
                 "{%0,%1,%2,%3}, {%4,%5,%6,%7}, {%8,%9}, {%0,%1,%2,%3};"
                 : "+f"(c[0]), "+f"(c[1]), "+f"(c[2]), "+f"(c[3])
                 : "r"(a[0]), "r"(a[1]), "r"(a[2]), "r"(a[3]), "r"(b[0]), "r"(b[1]));
}
__device__ __forceinline__ void redadd(float* p, float v){
    asm volatile("red.global.add.f32 [%0], %1;" :: "l"(p), "f"(v) : "memory");
}
#define CP_WAIT(N) asm volatile("cp.async.wait_group %0;" :: "n"(N) : "memory")

__device__ __forceinline__ uint4 pack8(const float4 a, const float4 b){
    uint4 v;
    __half2 h0 = __floats2half2_rn(a.x, a.y);
    __half2 h1 = __floats2half2_rn(a.z, a.w);
    __half2 h2 = __floats2half2_rn(b.x, b.y);
    __half2 h3 = __floats2half2_rn(b.z, b.w);
    v.x = *(uint32_t*)&h0; v.y = *(uint32_t*)&h1;
    v.z = *(uint32_t*)&h2; v.w = *(uint32_t*)&h3;
    return v;
}

// ============================ router + x convert + out zero-init ============================
__global__ __launch_bounds__(256) void router_convert_kernel(
    const float4* __restrict__ x4, const float* __restrict__ rw,
    const float* __restrict__ rb,  uint2* __restrict__ x16,
    float4* __restrict__ out4)
{
    int n = blockIdx.x;
    int tid = threadIdx.x;
    __shared__ float xs[D_DIM];
    __shared__ float lg[E_NUM];

    // zero-init this token's output row (down_mma accumulates into it via RED)
    out4[(size_t)n * (D_DIM / 4) + tid] = make_float4(0.f, 0.f, 0.f, 0.f);

    float4 v = x4[(size_t)n * (D_DIM / 4) + tid];
    ((float4*)xs)[tid] = v;
    __half2 ha = __floats2half2_rn(v.x, v.y);
    __half2 hb = __floats2half2_rn(v.z, v.w);
    uint2 o; o.x = *(uint32_t*)&ha; o.y = *(uint32_t*)&hb;
    x16[(size_t)n * (D_DIM / 4) + tid] = o;
    __syncthreads();

    int w = tid >> 5, lane = tid & 31;
    const float* wr = rw + (size_t)w * D_DIM;
    float s = 0.f;
    for (int i = lane; i < D_DIM; i += 32) s += xs[i] * wr[i];
    #pragma unroll
    for (int off = 16; off; off >>= 1) s += __shfl_xor_sync(0xffffffff, s, off);
    if (lane == 0) lg[w] = s;
    __syncthreads();

    if (tid == 0) {
        float l[E_NUM];
        #pragma unroll
        for (int e = 0; e < E_NUM; e++) l[e] = lg[e];

        int e0 = 0; float b0 = l[0] + rb[0];
        #pragma unroll
        for (int e = 1; e < E_NUM; e++) { float be = l[e] + rb[e]; if (be > b0) { b0 = be; e0 = e; } }
        int e1 = -1; float b1 = -1e30f;
        #pragma unroll
        for (int e = 0; e < E_NUM; e++) {
            if (e == e0) continue;
            float be = l[e] + rb[e];
            if (be > b1) { b1 = be; e1 = e; }
        }

        float l0 = l[e0], l1 = l[e1];
        float m2 = fmaxf(l0, l1);
        float w0 = expf(l0 - m2), w1 = expf(l1 - m2);
        float inv = 1.f / (w0 + w1);
        w0 *= inv; w1 *= inv;

        float mx = l[0];
        #pragma unroll
        for (int e = 1; e < E_NUM; e++) mx = fmaxf(mx, l[e]);
        float pe[E_NUM]; float se = 0.f;
        #pragma unroll
        for (int e = 0; e < E_NUM; e++) { pe[e] = expf(l[e] - mx); se += pe[e]; }
        float z = mx + logf(se);
        float invse = 1.f / se;
        g_z[n] = z;
        #pragma unroll
        for (int e = 0; e < E_NUM; e++) g_probs[n * E_NUM + e] = pe[e] * invse;

        g_topk[n * 2 + 0] = e0; g_topk[n * 2 + 1] = e1;
        g_wts[n * 2 + 0]  = w0; g_wts[n * 2 + 1]  = w1;
    }
}

// ============================ finalize + scatter (single block, parallel) ============================
__global__ __launch_bounds__(256) void finalize_scatter_kernel(
    float* __restrict__ out_scalars, int have_scalars)
{
    __shared__ int scnt[E_NUM];
    __shared__ int scur[E_NUM];
    __shared__ float red[9 * 256];
    __shared__ float sres[9];
    int tid = threadIdx.x;
    if (tid < E_NUM) scnt[tid] = 0;
    __syncthreads();

    for (int i = tid; i < NK; i += 256) atomicAdd(&scnt[g_topk[i]], 1);

    float pz = 0.f;
    float pp[E_NUM];
    #pragma unroll
    for (int e = 0; e < E_NUM; e++) pp[e] = 0.f;
    for (int n = tid; n < N_TOK; n += 256) {
        float z = g_z[n];
        pz += z * z;
        #pragma unroll
        for (int e = 0; e < E_NUM; e++) pp[e] += g_probs[n * E_NUM + e];
    }
    red[tid] = pz;
    #pragma unroll
    for (int e = 0; e < E_NUM; e++) red[(e + 1) * 256 + tid] = pp[e];
    __syncthreads();

    if (tid == 0) {
        int acc = 0;
        #pragma unroll
        for (int e = 0; e < E_NUM; e++) {
            g_off[e] = acc; g_cnt[e] = scnt[e]; scur[e] = acc;
            acc += scnt[e];
        }
    }
    if (tid < 9) {
        float s = 0.f;
        #pragma unroll 8
        for (int j = 0; j < 256; j++) s += red[tid * 256 + j];
        sres[tid] = s;
    }
    __syncthreads();

    if (tid == 0 && have_scalars) {
        float lb = 0.f;
        #pragma unroll
        for (int e = 0; e < E_NUM; e++)
            lb += (sres[e + 1] / (float)N_TOK) * ((float)scnt[e] / (float)N_TOK);
        lb *= (float)E_NUM;
        out_scalars[0] = 0.f;
        out_scalars[1] = sres[0] / (float)N_TOK * Z_COEF;
        out_scalars[2] = lb;
    }

    for (int i = tid; i < NK; i += 256) {
        int e = g_topk[i];
        int p = atomicAdd(&scur[e], 1);
        g_rowtok[p] = i >> 1;
        g_roww[p]   = g_wts[i];
    }
}

// ============================ tensor-core GEMMs (mma.sync HMMA) ============================
// BM=128, BK=32, 8 warps 4(M)x2(N), warp tile 32x32 per B matrix; both kernels
// process TWO 64-row B panels per stage so each stage issues 32 mma/warp.
#define LDR 80
#define GU_BG 10240
#define GU_BU 15360
#define GU_STG 20480

__global__ __launch_bounds__(256) void gateup_mma(
    const float* __restrict__ GateW, const float* __restrict__ UpW,
    const float* __restrict__ ShG,   const float* __restrict__ ShU)
{
    int grp = blockIdx.z;
    bool routed = grp < E_NUM;
    int rbase = routed ? g_off[grp] : 0;
    int rcnt  = routed ? g_cnt[grp] : N_TOK;
    int m0 = blockIdx.y * 128;
    if (m0 >= rcnt) return;
    int n0 = blockIdx.x * 64;

    const float* Wg = routed ? GateW + (size_t)grp * H_DIM * D_DIM : ShG;
    const float* Wu = routed ? UpW   + (size_t)grp * H_DIM * D_DIM : ShU;
    __half* Hout = routed ? g_h16 : g_hsh16;

    __shared__ __align__(16) char smem[2 * GU_STG];
    uint32_t sb = smem_u32(smem);
    int tid = threadIdx.x;

    int rA0 = tid >> 2, rA1 = rA0 + 64, seg = tid & 3;
    const __half *asrc0 = g_x16, *asrc1 = g_x16;
    uint32_t av0 = 0, av1 = 0;
    if (m0 + rA0 < rcnt) {
        int tk = routed ? g_rowtok[rbase + m0 + rA0] : m0 + rA0;
        asrc0 = g_x16 + (size_t)tk * D_DIM + seg * 8; av0 = 16;
    }
    if (m0 + rA1 < rcnt) {
        int tk = routed ? g_rowtok[rbase + m0 + rA1] : m0 + rA1;
        asrc1 = g_x16 + (size_t)tk * D_DIM + seg * 8; av1 = 16;
    }
    const float* gw = Wg + (size_t)(n0 + rA0) * D_DIM + seg * 8;
    const float* uw = Wu + (size_t)(n0 + rA0) * D_DIM + seg * 8;

    uint32_t dA0 = sb + rA0 * LDR + seg * 16;
    uint32_t dA1 = sb + rA1 * LDR + seg * 16;
    uint32_t dG  = sb + GU_BG + rA0 * LDR + seg * 16;
    uint32_t dU  = sb + GU_BU + rA0 * LDR + seg * 16;

    float4 wg0, wg1, wu0, wu1;
    auto ldg_w = [&](int s) {
        const float4* gp = (const float4*)(gw + s * 32);
        const float4* up = (const float4*)(uw + s * 32);
        wg0 = gp[0]; wg1 = gp[1];
        wu0 = up[0]; wu1 = up[1];
    };
    auto sts_w = [&](int buf) {
        uint32_t o = (uint32_t)buf * GU_STG;
        *(uint4*)(smem + (dG + o - sb)) = pack8(wg0, wg1);
        *(uint4*)(smem + (dU + o - sb)) = pack8(wu0, wu1);
    };
    auto cp_a = [&](int s) {
        uint32_t o = (uint32_t)(s & 1) * GU_STG;
        cp16(dA0 + o, asrc0 + s * 32, av0);
        cp16(dA1 + o, asrc1 + s * 32, av1);
        cp_commit();
    };

    const int S = D_DIM / 32;
    ldg_w(0); sts_w(0); cp_a(0);
    ldg_w(1); cp_a(1);

    int warp = tid >> 5, lane = tid & 31;
    int wm = warp & 3, wn = warp >> 2;
    int g = lane >> 3;
    int brow = ((g >> 1) << 3) + (lane & 7);
    int bks = (g & 1) << 4;

    float cg[2][4][4] = {}, cu[2][4][4] = {};

    #pragma unroll 1
    for (int s = 0; s < S; s++) {
        if (s + 1 < S) CP_WAIT(1);
        else           CP_WAIT(0);
        __syncthreads();
        uint32_t o = sb + (uint32_t)(s & 1) * GU_STG;

        uint32_t a[2][2][4];
        #pragma unroll
        for (int mt = 0; mt < 2; mt++)
            #pragma unroll
            for (int kt = 0; kt < 2; kt++)
                ldsm4(a[mt][kt], o + (wm * 32 + mt * 16 + (lane & 15)) * LDR + kt * 32 + (lane >> 4) * 16);

        uint32_t bg[2][2][4], bu[2][2][4];
        #pragma unroll
        for (int nt = 0; nt < 2; nt++)
            #pragma unroll
            for (int kt = 0; kt < 2; kt++) {
                uint32_t ro = (wn * 32 + nt * 16 + brow) * LDR + kt * 32 + bks;
                ldsm4(bg[nt][kt], o + GU_BG + ro);
                ldsm4(bu[nt][kt], o + GU_BU + ro);
            }

        #pragma unroll
        for (int mt = 0; mt < 2; mt++)
            #pragma unroll
            for (int nt = 0; nt < 2; nt++)
                #pragma unroll
                for (int kt = 0; kt < 2; kt++) {
                    mma16816(cg[mt][nt * 2 + 0], a[mt][kt], &bg[nt][kt][0]);
                    mma16816(cg[mt][nt * 2 + 1], a[mt][kt], &bg[nt][kt][2]);
                    mma16816(cu[mt][nt * 2 + 0], a[mt][kt], &bu[nt][kt][0]);
                    mma16816(cu[mt][nt * 2 + 1], a[mt][kt], &bu[nt][kt][2]);
                }

        if (s + 1 < S) sts_w((s + 1) & 1);
        __syncthreads();
        if (s + 2 < S) { cp_a(s + 2); ldg_w(s + 2); }
    }

    #pragma unroll
    for (int mt = 0; mt < 2; mt++) {
        int rbaserow = m0 + wm * 32 + mt * 16 + (lane >> 2);
        #pragma unroll
        for (int h = 0; h < 2; h++) {
            int r = rbaserow + h * 8;
            if (r >= rcnt) continue;
            __half* hp = Hout + (size_t)(rbase + r) * H_DIM + n0 + wn * 32 + (lane & 3) * 2;
            #pragma unroll
            for (int j = 0; j < 4; j++) {
                float g0 = cg[mt][j][h * 2 + 0], g1 = cg[mt][j][h * 2 + 1];
                float u0 = cu[mt][j][h * 2 + 0], u1 = cu[mt][j][h * 2 + 1];
                float h0 = g0 * u0 / (1.f + __expf(-g0));
                float h1 = g1 * u1 / (1.f + __expf(-g1));
                *(__half2*)(hp + j * 8) = __floats2half2_rn(h0, h1);
            }
        }
    }
}

// down: BN=128 via two 64-row panels of Wd; epilogue RED-accumulates into out.
__global__ __launch_bounds__(256) void down_mma(
    const float* __restrict__ DownW, const float* __restrict__ ShD,
    float* __restrict__ Out)
{
    int grp = blockIdx.z;
    bool routed = grp < E_NUM;
    int rbase = routed ? g_off[grp] : 0;
    int rcnt  = routed ? g_cnt[grp] : N_TOK;
    int m0 = blockIdx.y * 128;
    if (m0 >= rcnt) return;
    int n0 = blockIdx.x * 128;

    const float* Wd  = routed ? DownW + (size_t)grp * D_DIM * H_DIM : ShD;
    const __half* Hin = routed ? g_h16 : g_hsh16;

    __shared__ __align__(16) char smem[2 * GU_STG];
    uint32_t sb = smem_u32(smem);
    int tid = threadIdx.x;

    int rA0 = tid >> 2, rA1 = rA0 + 64, seg = tid & 3;
    const __half *asrc0 = Hin, *asrc1 = Hin;
    uint32_t av0 = 0, av1 = 0;
    if (m0 + rA0 < rcnt) { asrc0 = Hin + (size_t)(rbase + m0 + rA0) * H_DIM + seg * 8; av0 = 16; }
    if (m0 + rA1 < rcnt) { asrc1 = Hin + (size_t)(rbase + m0 + rA1) * H_DIM + seg * 8; av1 = 16; }
    const float* lw = Wd + (size_t)(n0 + rA0) * H_DIM + seg * 8;
    const float* hw = Wd + (size_t)(n0 + 64 + rA0) * H_DIM + seg * 8;

    uint32_t dA0 = sb + rA0 * LDR + seg * 16;
    uint32_t dA1 = sb + rA1 * LDR + seg * 16;
    uint32_t dL  = sb + GU_BG + rA0 * LDR + seg * 16;
    uint32_t dH  = sb + GU_BU + rA0 * LDR + seg * 16;

    float4 wl0, wl1, wh0, wh1;
    auto ldg_w = [&](int s) {
        const float4* lp = (const float4*)(lw + s * 32);
        const float4* hp = (const float4*)(hw + s * 32);
        wl0 = lp[0]; wl1 = lp[1];
        wh0 = hp[0]; wh1 = hp[1];
    };
    auto sts_w = [&](int buf) {
        uint32_t o = (uint32_t)buf * GU_STG;
        *(uint4*)(smem + (dL + o - sb)) = pack8(wl0, wl1);
        *(uint4*)(smem + (dH + o - sb)) = pack8(wh0, wh1);
    };
    auto cp_a = [&](int s) {
        uint32_t o = (uint32_t)(s & 1) * GU_STG;
        cp16(dA0 + o, asrc0 + s * 32, av0);
        cp16(dA1 + o, asrc1 + s * 32, av1);
        cp_commit();
    };

    const int S = H_DIM / 32;
    ldg_w(0); sts_w(0); cp_a(0);
    ldg_w(1); cp_a(1);

    int warp = tid >> 5, lane = tid & 31;
    int wm = warp & 3, wn = warp >> 2;
    int g = lane >> 3;
    int brow = ((g >> 1) << 3) + (lane & 7);
    int bks = (g & 1) << 4;

    float cl[2][4][4] = {}, ch[2][4][4] = {};

    #pragma unroll 1
    for (int s = 0; s < S; s++) {
        if (s + 1 < S) CP_WAIT(1);
        else           CP_WAIT(0);
        __syncthreads();
        uint32_t o = sb + (uint32_t)(s & 1) * GU_STG;

        uint32_t a[2][2][4];
        #pragma unroll
        for (int mt = 0; mt < 2; mt++)
            #pragma unroll
            for (int kt = 0; kt < 2; kt++)
                ldsm4(a[mt][kt], o + (wm * 32 + mt * 16 + (lane & 15)) * LDR + kt * 32 + (lane >> 4) * 16);

        uint32_t bl[2][2][4], bh[2][2][4];
        #pragma unroll
        for (int nt = 0; nt < 2; nt++)
            #pragma unroll
            for (int kt = 0; kt < 2; kt++) {
                uint32_t ro = (wn * 32 + nt * 16 + brow) * LDR + kt * 32 + bks;
                ldsm4(bl[nt][kt], o + GU_BG + ro);
                ldsm4(bh[nt][kt], o + GU_BU + ro);
            }

        #pragma unroll
        for (int mt = 0; mt < 2; mt++)
            #pragma unroll
            for (int nt = 0; nt < 2; nt++)
                #pragma unroll
                for (int kt = 0; kt < 2; kt++) {
                    mma16816(cl[mt][nt * 2 + 0], a[mt][kt], &bl[nt][kt][0]);
                    mma16816(cl[mt][nt * 2 + 1], a[mt][kt], &bl[nt][kt][2]);
                    mma16816(ch[mt][nt * 2 + 0], a[mt][kt], &bh[nt][kt][0]);
                    mma16816(ch[mt][nt * 2 + 1], a[mt][kt], &bh[nt][kt][2]);
                }

        if (s + 1 < S) sts_w((s + 1) & 1);
        __syncthreads();
        if (s + 2 < S) { cp_a(s + 2); ldg_w(s + 2); }
    }

    #pragma unroll
    for (int mt = 0; mt < 2; mt++) {
        int rbaserow = m0 + wm * 32 + mt * 16 + (lane >> 2);
        #pragma unroll
        for (int h = 0; h < 2; h++) {
            int r = rbaserow + h * 8;
            if (r >= rcnt) continue;
            float w = 1.f;
            int tok;
            if (routed) { w = g_roww[rbase + r]; tok = g_rowtok[rbase + r]; }
            else        { tok = r; }
            float* op = Out + (size_t)tok * D_DIM + n0 + wn * 32 + (lane & 3) * 2;
            #pragma unroll
            for (int j = 0; j < 4; j++) {
                redadd(op + j * 8 + 0,      cl[mt][j][h * 2 + 0] * w);
                redadd(op + j * 8 + 1,      cl[mt][j][h * 2 + 1] * w);
                redadd(op + 64 + j * 8 + 0, ch[mt][j][h * 2 + 0] * w);
                redadd(op + 64 + j * 8 + 1, ch[mt][j][h * 2 + 1] * w);
            }
        }
    }
}

// ============================ launch ============================
extern "C" void kernel_launch(void* const* d_in, const int* in_sizes, int n_in,
                              void* d_out, int out_size) {
    const float* x      = (const float*)d_in[0];
    const float* rw     = (const float*)d_in[1];
    const float* rb     = (const float*)d_in[2];
    const float* gate_w = (const float*)d_in[3];
    const float* up_w   = (const float*)d_in[4];
    const float* down_w = (const float*)d_in[5];
    const float* shg    = (const float*)d_in[6];
    const float* shu    = (const float*)d_in[7];
    const float* shd    = (const float*)d_in[8];
    float* out = (float*)d_out;

    const int hid_elems = N_TOK * D_DIM;
    int have_scalars = (out_size >= hid_elems + 3) ? 1 : 0;

    void* p_x16;
    cudaGetSymbolAddress(&p_x16, g_x16);

    router_convert_kernel<<<N_TOK, 256>>>((const float4*)x, rw, rb, (uint2*)p_x16,
                                          (float4*)out);
    finalize_scatter_kernel<<<1, 256>>>(out + hid_elems, have_scalars);

    gateup_mma<<<dim3(H_DIM / 64, 16, 9), 256>>>(gate_w, up_w, shg, shu);
    down_mma<<<dim3(D_DIM / 128, 16, 9), 256>>>(down_w, shd, out);
}

// round 15
// speedup vs baseline: 1.3608x; 1.0773x over previous
#include <cuda_runtime.h>
#include <cuda_fp16.h>
#include <math.h>
#include <stdint.h>

#define N_TOK 2048
#define D_DIM 1024
#define E_NUM 8
#define K_TOP 2
#define H_DIM 2048
#define NK (N_TOK*K_TOP)
#define Z_COEF 1e-4f

// ---------------- fp16 scratch (device globals; no allocs allowed) ----------------
__device__ __half g_x16[(size_t)N_TOK*D_DIM];
__device__ __half g_h16[(size_t)NK*H_DIM];
__device__ __half g_hsh16[(size_t)N_TOK*H_DIM];

// ---------------- router scratch ----------------
__device__ int   g_topk[NK];
__device__ float g_wts[NK];
__device__ float g_probs[(size_t)N_TOK*E_NUM];
__device__ float g_z[N_TOK];
__device__ int   g_cnt[E_NUM];
__device__ int   g_off[E_NUM];
__device__ int   g_rowtok[NK];
__device__ float g_roww[NK];

// ============================ PTX helpers ============================
__device__ __forceinline__ uint32_t smem_u32(const void* p){
    uint32_t a;
    asm("{ .reg .u64 t; cvta.to.shared.u64 t, %1; cvt.u32.u64 %0, t; }" : "=r"(a) : "l"(p));
    return a;
}
__device__ __forceinline__ void cp16(uint32_t dst, const void* src, uint32_t sz){
    asm volatile("cp.async.cg.shared.global [%0], [%1], 16, %2;"
                 :: "r"(dst), "l"(src), "r"(sz) : "memory");
}
__device__ __forceinline__ void cp_commit(){ asm volatile("cp.async.commit_group;" ::: "memory"); }
__device__ __forceinline__ void ldsm4(uint32_t* r, uint32_t addr){
    asm volatile("ldmatrix.sync.aligned.m8n8.x4.shared.b16 {%0,%1,%2,%3}, [%4];"
                 : "=r"(r[0]), "=r"(r[1]), "=r"(r[2]), "=r"(r[3]) : "r"(addr));
}
__device__ __forceinline__ void mma16816(float* c, const uint32_t* a, const uint32_t* b){
    asm volatile("mma.sync.aligned.m16n8k16.row.col.f32.f16.f16.f32 "
                 "{%0,%1,%2,%3}, {%4,%5,%6,%7}, {%8,%9}, {%0,%1,%2,%3};"
                 : "+f"(c[0]), "+f"(c[1]), "+f"(c[2]), "+f"(c[3])
                 : "r"(a[0]), "r"(a[1]), "r"(a[2]), "r"(a[3]), "r"(b[0]), "r"(b[1]));
}
__device__ __forceinline__ void redadd(float* p, float v){
    asm volatile("red.global.add.f32 [%0], %1;" :: "l"(p), "f"(v) : "memory");
}
#define CP_WAIT(N) asm volatile("cp.async.wait_group %0;" :: "n"(N) : "memory")

__device__ __forceinline__ uint4 pack8(const float4 a, const float4 b){
    uint4 v;
    __half2 h0 = __floats2half2_rn(a.x, a.y);
    __half2 h1 = __floats2half2_rn(a.z, a.w);
    __half2 h2 = __floats2half2_rn(b.x, b.y);
    __half2 h3 = __floats2half2_rn(b.z, b.w);
    v.x = *(uint32_t*)&h0; v.y = *(uint32_t*)&h1;
    v.z = *(uint32_t*)&h2; v.w = *(uint32_t*)&h3;
    return v;
}

// ============================ router + x convert + out zero-init ============================
__global__ __launch_bounds__(256) void router_convert_kernel(
    const float4* __restrict__ x4, const float* __restrict__ rw,
    const float* __restrict__ rb,  uint2* __restrict__ x16,
    float4* __restrict__ out4)
{
    int n = blockIdx.x;
    int tid = threadIdx.x;
    __shared__ float xs[D_DIM];
    __shared__ float lg[E_NUM];

    out4[(size_t)n * (D_DIM / 4) + tid] = make_float4(0.f, 0.f, 0.f, 0.f);

    float4 v = x4[(size_t)n * (D_DIM / 4) + tid];
    ((float4*)xs)[tid] = v;
    __half2 ha = __floats2half2_rn(v.x, v.y);
    __half2 hb = __floats2half2_rn(v.z, v.w);
    uint2 o; o.x = *(uint32_t*)&ha; o.y = *(uint32_t*)&hb;
    x16[(size_t)n * (D_DIM / 4) + tid] = o;
    __syncthreads();

    int w = tid >> 5, lane = tid & 31;
    const float* wr = rw + (size_t)w * D_DIM;
    float s = 0.f;
    for (int i = lane; i < D_DIM; i += 32) s += xs[i] * wr[i];
    #pragma unroll
    for (int off = 16; off; off >>= 1) s += __shfl_xor_sync(0xffffffff, s, off);
    if (lane == 0) lg[w] = s;
    __syncthreads();

    if (tid == 0) {
        float l[E_NUM];
        #pragma unroll
        for (int e = 0; e < E_NUM; e++) l[e] = lg[e];

        int e0 = 0; float b0 = l[0] + rb[0];
        #pragma unroll
        for (int e = 1; e < E_NUM; e++) { float be = l[e] + rb[e]; if (be > b0) { b0 = be; e0 = e; } }
        int e1 = -1; float b1 = -1e30f;
        #pragma unroll
        for (int e = 0; e < E_NUM; e++) {
            if (e == e0) continue;
            float be = l[e] + rb[e];
            if (be > b1) { b1 = be; e1 = e; }
        }

        float l0 = l[e0], l1 = l[e1];
        float m2 = fmaxf(l0, l1);
        float w0 = expf(l0 - m2), w1 = expf(l1 - m2);
        float inv = 1.f / (w0 + w1);
        w0 *= inv; w1 *= inv;

        float mx = l[0];
        #pragma unroll
        for (int e = 1; e < E_NUM; e++) mx = fmaxf(mx, l[e]);
        float pe[E_NUM]; float se = 0.f;
        #pragma unroll
        for (int e = 0; e < E_NUM; e++) { pe[e] = expf(l[e] - mx); se += pe[e]; }
        float z = mx + logf(se);
        float invse = 1.f / se;
        g_z[n] = z;
        #pragma unroll
        for (int e = 0; e < E_NUM; e++) g_probs[n * E_NUM + e] = pe[e] * invse;

        g_topk[n * 2 + 0] = e0; g_topk[n * 2 + 1] = e1;
        g_wts[n * 2 + 0]  = w0; g_wts[n * 2 + 1]  = w1;
    }
}

// ============================ finalize + scatter (single block, parallel) ============================
__global__ __launch_bounds__(256) void finalize_scatter_kernel(
    float* __restrict__ out_scalars, int have_scalars)
{
    __shared__ int scnt[E_NUM];
    __shared__ int scur[E_NUM];
    __shared__ float red[9 * 256];
    __shared__ float sres[9];
    int tid = threadIdx.x;
    if (tid < E_NUM) scnt[tid] = 0;
    __syncthreads();

    for (int i = tid; i < NK; i += 256) atomicAdd(&scnt[g_topk[i]], 1);

    float pz = 0.f;
    float pp[E_NUM];
    #pragma unroll
    for (int e = 0; e < E_NUM; e++) pp[e] = 0.f;
    for (int n = tid; n < N_TOK; n += 256) {
        float z = g_z[n];
        pz += z * z;
        #pragma unroll
        for (int e = 0; e < E_NUM; e++) pp[e] += g_probs[n * E_NUM + e];
    }
    red[tid] = pz;
    #pragma unroll
    for (int e = 0; e < E_NUM; e++) red[(e + 1) * 256 + tid] = pp[e];
    __syncthreads();

    if (tid == 0) {
        int acc = 0;
        #pragma unroll
        for (int e = 0; e < E_NUM; e++) {
            g_off[e] = acc; g_cnt[e] = scnt[e]; scur[e] = acc;
            acc += scnt[e];
        }
    }
    if (tid < 9) {
        float s = 0.f;
        #pragma unroll 8
        for (int j = 0; j < 256; j++) s += red[tid * 256 + j];
        sres[tid] = s;
    }
    __syncthreads();

    if (tid == 0 && have_scalars) {
        float lb = 0.f;
        #pragma unroll
        for (int e = 0; e < E_NUM; e++)
            lb += (sres[e + 1] / (float)N_TOK) * ((float)scnt[e] / (float)N_TOK);
        lb *= (float)E_NUM;
        out_scalars[0] = 0.f;
        out_scalars[1] = sres[0] / (float)N_TOK * Z_COEF;
        out_scalars[2] = lb;
    }

    for (int i = tid; i < NK; i += 256) {
        int e = g_topk[i];
        int p = atomicAdd(&scur[e], 1);
        g_rowtok[p] = i >> 1;
        g_roww[p]   = g_wts[i];
    }
}

// ============================ tensor-core GEMMs (mma.sync HMMA) ============================
// BM=128, BK=32, 8 warps 4(M)x2(N), warp tile 32x32 per B matrix; both kernels
// process TWO 64-row B panels per stage so each stage issues 32 mma/warp.
#define LDR 80
#define GU_BG 10240
#define GU_BU 15360
#define GU_STG 20480

__global__ __launch_bounds__(256) void gateup_mma(
    const float* __restrict__ GateW, const float* __restrict__ UpW,
    const float* __restrict__ ShG,   const float* __restrict__ ShU)
{
    int grp = blockIdx.z;
    bool routed = grp < E_NUM;
    int rbase = routed ? g_off[grp] : 0;
    int rcnt  = routed ? g_cnt[grp] : N_TOK;
    int m0 = blockIdx.y * 128;
    if (m0 >= rcnt) return;
    int n0 = blockIdx.x * 64;

    const float* Wg = routed ? GateW + (size_t)grp * H_DIM * D_DIM : ShG;
    const float* Wu = routed ? UpW   + (size_t)grp * H_DIM * D_DIM : ShU;
    __half* Hout = routed ? g_h16 : g_hsh16;

    __shared__ __align__(16) char smem[2 * GU_STG];
    uint32_t sb = smem_u32(smem);
    int tid = threadIdx.x;

    int rA0 = tid >> 2, rA1 = rA0 + 64, seg = tid & 3;
    const __half *asrc0 = g_x16, *asrc1 = g_x16;
    uint32_t av0 = 0, av1 = 0;
    if (m0 + rA0 < rcnt) {
        int tk = routed ? g_rowtok[rbase + m0 + rA0] : m0 + rA0;
        asrc0 = g_x16 + (size_t)tk * D_DIM + seg * 8; av0 = 16;
    }
    if (m0 + rA1 < rcnt) {
        int tk = routed ? g_rowtok[rbase + m0 + rA1] : m0 + rA1;
        asrc1 = g_x16 + (size_t)tk * D_DIM + seg * 8; av1 = 16;
    }
    const float* gw = Wg + (size_t)(n0 + rA0) * D_DIM + seg * 8;
    const float* uw = Wu + (size_t)(n0 + rA0) * D_DIM + seg * 8;

    uint32_t dA0 = sb + rA0 * LDR + seg * 16;
    uint32_t dA1 = sb + rA1 * LDR + seg * 16;
    uint32_t dG  = sb + GU_BG + rA0 * LDR + seg * 16;
    uint32_t dU  = sb + GU_BU + rA0 * LDR + seg * 16;

    float4 wg0, wg1, wu0, wu1;
    auto ldg_w = [&](int s) {
        const float4* gp = (const float4*)(gw + s * 32);
        const float4* up = (const float4*)(uw + s * 32);
        wg0 = gp[0]; wg1 = gp[1];
        wu0 = up[0]; wu1 = up[1];
    };
    auto sts_w = [&](int buf) {
        uint32_t o = (uint32_t)buf * GU_STG;
        *(uint4*)(smem + (dG + o - sb)) = pack8(wg0, wg1);
        *(uint4*)(smem + (dU + o - sb)) = pack8(wu0, wu1);
    };
    auto cp_a = [&](int s) {
        uint32_t o = (uint32_t)(s & 1) * GU_STG;
        cp16(dA0 + o, asrc0 + s * 32, av0);
        cp16(dA1 + o, asrc1 + s * 32, av1);
        cp_commit();
    };

    const int S = D_DIM / 32;
    ldg_w(0); sts_w(0); cp_a(0);
    ldg_w(1); cp_a(1);

    int warp = tid >> 5, lane = tid & 31;
    int wm = warp & 3, wn = warp >> 2;
    int g = lane >> 3;
    int brow = ((g >> 1) << 3) + (lane & 7);
    int bks = (g & 1) << 4;

    float cg[2][4][4] = {}, cu[2][4][4] = {};

    #pragma unroll 1
    for (int s = 0; s < S; s++) {
        if (s + 1 < S) CP_WAIT(1);
        else           CP_WAIT(0);
        __syncthreads();
        uint32_t o = sb + (uint32_t)(s & 1) * GU_STG;

        uint32_t a[2][2][4];
        #pragma unroll
        for (int mt = 0; mt < 2; mt++)
            #pragma unroll
            for (int kt = 0; kt < 2; kt++)
                ldsm4(a[mt][kt], o + (wm * 32 + mt * 16 + (lane & 15)) * LDR + kt * 32 + (lane >> 4) * 16);

        uint32_t bg[2][2][4], bu[2][2][4];
        #pragma unroll
        for (int nt = 0; nt < 2; nt++)
            #pragma unroll
            for (int kt = 0; kt < 2; kt++) {
                uint32_t ro = (wn * 32 + nt * 16 + brow) * LDR + kt * 32 + bks;
                ldsm4(bg[nt][kt], o + GU_BG + ro);
                ldsm4(bu[nt][kt], o + GU_BU + ro);
            }

        #pragma unroll
        for (int mt = 0; mt < 2; mt++)
            #pragma unroll
            for (int nt = 0; nt < 2; nt++)
                #pragma unroll
                for (int kt = 0; kt < 2; kt++) {
                    mma16816(cg[mt][nt * 2 + 0], a[mt][kt], &bg[nt][kt][0]);
                    mma16816(cg[mt][nt * 2 + 1], a[mt][kt], &bg[nt][kt][2]);
                    mma16816(cu[mt][nt * 2 + 0], a[mt][kt], &bu[nt][kt][0]);
                    mma16816(cu[mt][nt * 2 + 1], a[mt][kt], &bu[nt][kt][2]);
                }

        if (s + 1 < S) sts_w((s + 1) & 1);
        __syncthreads();
        if (s + 2 < S) { cp_a(s + 2); ldg_w(s + 2); }
    }

    #pragma unroll
    for (int mt = 0; mt < 2; mt++) {
        int rbaserow = m0 + wm * 32 + mt * 16 + (lane >> 2);
        #pragma unroll
        for (int h = 0; h < 2; h++) {
            int r = rbaserow + h * 8;
            if (r >= rcnt) continue;
            __half* hp = Hout + (size_t)(rbase + r) * H_DIM + n0 + wn * 32 + (lane & 3) * 2;
            #pragma unroll
            for (int j = 0; j < 4; j++) {
                float g0 = cg[mt][j][h * 2 + 0], g1 = cg[mt][j][h * 2 + 1];
                float u0 = cu[mt][j][h * 2 + 0], u1 = cu[mt][j][h * 2 + 1];
                float h0 = g0 * u0 / (1.f + __expf(-g0));
                float h1 = g1 * u1 / (1.f + __expf(-g1));
                *(__half2*)(hp + j * 8) = __floats2half2_rn(h0, h1);
            }
        }
    }
}

// down: BN=128 (two 64-row Wd panels), split-K=2 (z = grp + 9*kpart),
// epilogue RED-accumulates partials into out.
#define DN_KSPLIT 2
#define DN_KLEN   (H_DIM / DN_KSPLIT)   // 1024

__global__ __launch_bounds__(256) void down_mma(
    const float* __restrict__ DownW, const float* __restrict__ ShD,
    float* __restrict__ Out)
{
    int zz = blockIdx.z;
    int grp = zz % 9;
    int kp  = zz / 9;
    bool routed = grp < E_NUM;
    int rbase = routed ? g_off[grp] : 0;
    int rcnt  = routed ? g_cnt[grp] : N_TOK;
    int m0 = blockIdx.y * 128;
    if (m0 >= rcnt) return;
    int n0 = blockIdx.x * 128;
    int k0 = kp * DN_KLEN;

    const float* Wd  = routed ? DownW + (size_t)grp * D_DIM * H_DIM : ShD;
    const __half* Hin = routed ? g_h16 : g_hsh16;

    __shared__ __align__(16) char smem[2 * GU_STG];
    uint32_t sb = smem_u32(smem);
    int tid = threadIdx.x;

    int rA0 = tid >> 2, rA1 = rA0 + 64, seg = tid & 3;
    const __half *asrc0 = Hin, *asrc1 = Hin;
    uint32_t av0 = 0, av1 = 0;
    if (m0 + rA0 < rcnt) { asrc0 = Hin + (size_t)(rbase + m0 + rA0) * H_DIM + k0 + seg * 8; av0 = 16; }
    if (m0 + rA1 < rcnt) { asrc1 = Hin + (size_t)(rbase + m0 + rA1) * H_DIM + k0 + seg * 8; av1 = 16; }
    const float* lw = Wd + (size_t)(n0 + rA0) * H_DIM + k0 + seg * 8;
    const float* hw = Wd + (size_t)(n0 + 64 + rA0) * H_DIM + k0 + seg * 8;

    uint32_t dA0 = sb + rA0 * LDR + seg * 16;
    uint32_t dA1 = sb + rA1 * LDR + seg * 16;
    uint32_t dL  = sb + GU_BG + rA0 * LDR + seg * 16;
    uint32_t dH  = sb + GU_BU + rA0 * LDR + seg * 16;

    float4 wl0, wl1, wh0, wh1;
    auto ldg_w = [&](int s) {
        const float4* lp = (const float4*)(lw + s * 32);
        const float4* hp = (const float4*)(hw + s * 32);
        wl0 = lp[0]; wl1 = lp[1];
        wh0 = hp[0]; wh1 = hp[1];
    };
    auto sts_w = [&](int buf) {
        uint32_t o = (uint32_t)buf * GU_STG;
        *(uint4*)(smem + (dL + o - sb)) = pack8(wl0, wl1);
        *(uint4*)(smem + (dH + o - sb)) = pack8(wh0, wh1);
    };
    auto cp_a = [&](int s) {
        uint32_t o = (uint32_t)(s & 1) * GU_STG;
        cp16(dA0 + o, asrc0 + s * 32, av0);
        cp16(dA1 + o, asrc1 + s * 32, av1);
        cp_commit();
    };

    const int S = DN_KLEN / 32;   // 32
    ldg_w(0); sts_w(0); cp_a(0);
    ldg_w(1); cp_a(1);

    int warp = tid >> 5, lane = tid & 31;
    int wm = warp & 3, wn = warp >> 2;
    int g = lane >> 3;
    int brow = ((g >> 1) << 3) + (lane & 7);
    int bks = (g & 1) << 4;

    float cl[2][4][4] = {}, ch[2][4][4] = {};

    #pragma unroll 1
    for (int s = 0; s < S; s++) {
        if (s + 1 < S) CP_WAIT(1);
        else           CP_WAIT(0);
        __syncthreads();
        uint32_t o = sb + (uint32_t)(s & 1) * GU_STG;

        uint32_t a[2][2][4];
        #pragma unroll
        for (int mt = 0; mt < 2; mt++)
            #pragma unroll
            for (int kt = 0; kt < 2; kt++)
                ldsm4(a[mt][kt], o + (wm * 32 + mt * 16 + (lane & 15)) * LDR + kt * 32 + (lane >> 4) * 16);

        uint32_t bl[2][2][4], bh[2][2][4];
        #pragma unroll
        for (int nt = 0; nt < 2; nt++)
            #pragma unroll
            for (int kt = 0; kt < 2; kt++) {
                uint32_t ro = (wn * 32 + nt * 16 + brow) * LDR + kt * 32 + bks;
                ldsm4(bl[nt][kt], o + GU_BG + ro);
                ldsm4(bh[nt][kt], o + GU_BU + ro);
            }

        #pragma unroll
        for (int mt = 0; mt < 2; mt++)
            #pragma unroll
            for (int nt = 0; nt < 2; nt++)
                #pragma unroll
                for (int kt = 0; kt < 2; kt++) {
                    mma16816(cl[mt][nt * 2 + 0], a[mt][kt], &bl[nt][kt][0]);
                    mma16816(cl[mt][nt * 2 + 1], a[mt][kt], &bl[nt][kt][2]);
                    mma16816(ch[mt][nt * 2 + 0], a[mt][kt], &bh[nt][kt][0]);
                    mma16816(ch[mt][nt * 2 + 1], a[mt][kt], &bh[nt][kt][2]);
                }

        if (s + 1 < S) sts_w((s + 1) & 1);
        __syncthreads();
        if (s + 2 < S) { cp_a(s + 2); ldg_w(s + 2); }
    }

    #pragma unroll
    for (int mt = 0; mt < 2; mt++) {
        int rbaserow = m0 + wm * 32 + mt * 16 + (lane >> 2);
        #pragma unroll
        for (int h = 0; h < 2; h++) {
            int r = rbaserow + h * 8;
            if (r >= rcnt) continue;
            float w = 1.f;
            int tok;
            if (routed) { w = g_roww[rbase + r]; tok = g_rowtok[rbase + r]; }
            else        { tok = r; }
            float* op = Out + (size_t)tok * D_DIM + n0 + wn * 32 + (lane & 3) * 2;
            #pragma unroll
            for (int j = 0; j < 4; j++) {
                redadd(op + j * 8 + 0,      cl[mt][j][h * 2 + 0] * w);
                redadd(op + j * 8 + 1,      cl[mt][j][h * 2 + 1] * w);
                redadd(op + 64 + j * 8 + 0, ch[mt][j][h * 2 + 0] * w);
                redadd(op + 64 + j * 8 + 1, ch[mt][j][h * 2 + 1] * w);
            }
        }
    }
}

// ============================ launch ============================
extern "C" void kernel_launch(void* const* d_in, const int* in_sizes, int n_in,
                              void* d_out, int out_size) {
    const float* x      = (const float*)d_in[0];
    const float* rw     = (const float*)d_in[1];
    const float* rb     = (const float*)d_in[2];
    const float* gate_w = (const float*)d_in[3];
    const float* up_w   = (const float*)d_in[4];
    const float* down_w = (const float*)d_in[5];
    const float* shg    = (const float*)d_in[6];
    const float* shu    = (const float*)d_in[7];
    const float* shd    = (const float*)d_in[8];
    float* out = (float*)d_out;

    const int hid_elems = N_TOK * D_DIM;
    int have_scalars = (out_size >= hid_elems + 3) ? 1 : 0;

    void* p_x16;
    cudaGetSymbolAddress(&p_x16, g_x16);

    router_convert_kernel<<<N_TOK, 256>>>((const float4*)x, rw, rb, (uint2*)p_x16,
                                          (float4*)out);
    finalize_scatter_kernel<<<1, 256>>>(out + hid_elems, have_scalars);

    gateup_mma<<<dim3(H_DIM / 64, 16, 9), 256>>>(gate_w, up_w, shg, shu);
    down_mma<<<dim3(D_DIM / 128, 16, 9 * DN_KSPLIT), 256>>>(down_w, shd, out);
}